// round 1
// baseline (speedup 1.0000x reference)
#include <cuda_runtime.h>
#include <math.h>

// Problem dims (fixed by the reference).
namespace {
constexpr int Bsz  = 16;
constexpr int Ssz  = 2048;
constexpr int Hsz  = 1024;
constexpr int INsz = 1024;
constexpr int Msz  = Bsz * Ssz;   // 32768 rows
}

// Scratch: input currents I (B,S,H) and comb = [v, s] (B,S,2H).
__device__ float g_I[(size_t)Msz * Hsz];          // 128 MiB
__device__ float g_comb[(size_t)Msz * 2 * Hsz];   // 256 MiB

// ---------------------------------------------------------------------------
// Classic fp32 SIMT GEMM: C[M,N] = A[M,K] * B[K,N] + bias, optional tanh.
// Block tile 128x128, K-tile 8, 256 threads, 8x8 per-thread microtile.
// M, N multiples of 128; K multiple of 8. A, B row-major.
// ---------------------------------------------------------------------------
template<int KDIM, bool DO_TANH>
__global__ __launch_bounds__(256, 2)
void sgemm128(const float* __restrict__ A, const float* __restrict__ Bm,
              const float* __restrict__ bias, float* __restrict__ C, int N)
{
    constexpr int BM = 128, BN = 128, BK = 8, TM = 8, TN = 8;
    __shared__ float As[BK * BM];   // transposed A tile: As[k][m]
    __shared__ float Bs[BK * BN];   // Bs[k][n]

    const int tid  = threadIdx.x;
    const int crow = blockIdx.y * BM;
    const int ccol = blockIdx.x * BN;

    A  += (size_t)crow * KDIM;
    Bm += ccol;
    C  += (size_t)crow * N + ccol;

    // A tile loads: 128 rows x 8 cols = 1024 floats = 1 float4/thread
    const int iRA = tid >> 1;            // 0..127
    const int iCA = (tid & 1) * 4;       // 0 or 4
    // B tile loads: 8 rows x 128 cols = 1 float4/thread
    const int iRB = tid >> 5;            // 0..7
    const int iCB = (tid & 31) * 4;      // 0..124

    const int tRow = (tid >> 4) * TM;    // 0..120
    const int tCol = (tid & 15) * TN;    // 0..120

    float acc[TM][TN] = {};
    float rM[TM], rN[TN];

    for (int k0 = 0; k0 < KDIM; k0 += BK) {
        // Load A tile (transpose into As)
        float4 a4 = *reinterpret_cast<const float4*>(
            &A[(size_t)iRA * KDIM + k0 + iCA]);
        As[(iCA + 0) * BM + iRA] = a4.x;
        As[(iCA + 1) * BM + iRA] = a4.y;
        As[(iCA + 2) * BM + iRA] = a4.z;
        As[(iCA + 3) * BM + iRA] = a4.w;
        // Load B tile
        *reinterpret_cast<float4*>(&Bs[iRB * BN + iCB]) =
            *reinterpret_cast<const float4*>(&Bm[(size_t)(k0 + iRB) * N + iCB]);
        __syncthreads();

#pragma unroll
        for (int k = 0; k < BK; ++k) {
#pragma unroll
            for (int i = 0; i < TM; i += 4) {
                float4 m4 = *reinterpret_cast<const float4*>(&As[k * BM + tRow + i]);
                rM[i + 0] = m4.x; rM[i + 1] = m4.y;
                rM[i + 2] = m4.z; rM[i + 3] = m4.w;
            }
#pragma unroll
            for (int j = 0; j < TN; j += 4) {
                float4 n4 = *reinterpret_cast<const float4*>(&Bs[k * BN + tCol + j]);
                rN[j + 0] = n4.x; rN[j + 1] = n4.y;
                rN[j + 2] = n4.z; rN[j + 3] = n4.w;
            }
#pragma unroll
            for (int i = 0; i < TM; ++i)
#pragma unroll
                for (int j = 0; j < TN; ++j)
                    acc[i][j] = fmaf(rM[i], rN[j], acc[i][j]);
        }
        __syncthreads();
    }

    // Epilogue: bias (+ optional tanh), float4 stores
#pragma unroll
    for (int i = 0; i < TM; ++i) {
#pragma unroll
        for (int j = 0; j < TN; j += 4) {
            float4 v;
            v.x = acc[i][j + 0] + bias[ccol + tCol + j + 0];
            v.y = acc[i][j + 1] + bias[ccol + tCol + j + 1];
            v.z = acc[i][j + 2] + bias[ccol + tCol + j + 2];
            v.w = acc[i][j + 3] + bias[ccol + tCol + j + 3];
            if (DO_TANH) {
                v.x = tanhf(v.x); v.y = tanhf(v.y);
                v.z = tanhf(v.z); v.w = tanhf(v.w);
            }
            *reinterpret_cast<float4*>(&C[(size_t)(tRow + i) * N + tCol + j]) = v;
        }
    }
}

// ---------------------------------------------------------------------------
// Hysteresis leaky-integrate scan. One thread per (b,h); coalesced over h.
//   v_t = alpha*v_{t-1} + I_t ;  s flips at +/-thr (Schmitt trigger)
//   comb[b,t, 0:H] = v ; comb[b,t, H:2H] = s
// alpha = exp(-softplus(tau)) = 1/(1+exp(tau))
// ---------------------------------------------------------------------------
__global__ void hsru_scan(const float* __restrict__ leak_tau,
                          const float* __restrict__ thr_arr)
{
    const int h = blockIdx.x * blockDim.x + threadIdx.x;   // 0..H-1
    const int b = blockIdx.y;                              // 0..B-1
    const float alpha = 1.0f / (1.0f + expf(leak_tau[h]));
    const float th = thr_arr[h];

    float v = 0.0f, s = -1.0f;
    const float* Ip = g_I    + (size_t)b * Ssz * Hsz + h;
    float*       cp = g_comb + (size_t)b * Ssz * (2 * Hsz) + h;

    for (int t = 0; t < Ssz; ++t) {
        v = fmaf(alpha, v, Ip[(size_t)t * Hsz]);
        s = (v > th) ? 1.0f : ((v < -th) ? -1.0f : s);
        cp[(size_t)t * (2 * Hsz)]       = v;
        cp[(size_t)t * (2 * Hsz) + Hsz] = s;
    }
}

// ---------------------------------------------------------------------------
extern "C" void kernel_launch(void* const* d_in, const int* in_sizes, int n_in,
                              void* d_out, int out_size)
{
    const float* x        = (const float*)d_in[0];  // (B,S,IN)
    const float* W_in     = (const float*)d_in[1];  // (IN,H)
    const float* b_in     = (const float*)d_in[2];  // (H)
    const float* leak_tau = (const float*)d_in[3];  // (H)
    const float* thr      = (const float*)d_in[4];  // (H)
    const float* W_out    = (const float*)d_in[5];  // (2H,H)
    const float* b_out    = (const float*)d_in[6];  // (H)
    float* out = (float*)d_out;                     // (B,S,H)

    float *pI = nullptr, *pC = nullptr;
    cudaGetSymbolAddress((void**)&pI, g_I);
    cudaGetSymbolAddress((void**)&pC, g_comb);

    // GEMM1: I = x @ W_in + b_in
    {
        dim3 grid(Hsz / 128, Msz / 128);
        sgemm128<INsz, false><<<grid, 256>>>(x, W_in, b_in, pI, Hsz);
    }
    // Scan: comb = [v, s]
    {
        dim3 grid(Hsz / 256, Bsz);
        hsru_scan<<<grid, 256>>>(leak_tau, thr);
    }
    // GEMM2: out = tanh(comb @ W_out + b_out)
    {
        dim3 grid(Hsz / 128, Msz / 128);
        sgemm128<2 * Hsz, true><<<grid, 256>>>(pC, W_out, b_out, out, Hsz);
    }
}

// round 4
// speedup vs baseline: 1.9079x; 1.9079x over previous
#include <cuda_runtime.h>
#include <cuda_bf16.h>
#include <stdint.h>
#include <math.h>

// ---------------------------------------------------------------------------
// Problem dims
// ---------------------------------------------------------------------------
namespace {
constexpr int Bsz  = 16;
constexpr int Ssz  = 2048;
constexpr int Hsz  = 1024;
constexpr int INsz = 1024;
constexpr int Msz  = Bsz * Ssz;       // 32768
constexpr int NG   = 1024;
constexpr int GEMM2_SMEM = 2 * 32768; // double-buffered A+B bf16 tiles
}

// ---------------------------------------------------------------------------
// Scratch (__device__ globals; no allocation allowed)
// ---------------------------------------------------------------------------
__device__ float g_I[(size_t)Msz * Hsz];                   // 128 MiB
__device__ __nv_bfloat16 g_c1[(size_t)Msz * 2 * Hsz];      // [M][2048]: v | s
__device__ __nv_bfloat16 g_c2v[(size_t)Msz * Hsz];         // [M][1024]: v residual
__device__ __nv_bfloat16 g_Wo1[(size_t)Hsz * 2 * Hsz];     // [N=1024][K=2048]
__device__ __nv_bfloat16 g_Wo2[(size_t)Hsz * 2 * Hsz];

// ---------------------------------------------------------------------------
// PTX helpers (base sm_80+ features only)
// ---------------------------------------------------------------------------
#define SWZ128(o) ((o) ^ (((o) >> 3) & 0x70))

__device__ __forceinline__ uint32_t smem_u32(const void* p) {
    uint32_t a;
    asm("{ .reg .u64 t; cvta.to.shared.u64 t, %1; cvt.u32.u64 %0, t; }"
        : "=r"(a) : "l"(p));
    return a;
}
#define CP_ASYNC16(s, g) \
    asm volatile("cp.async.cg.shared.global [%0], [%1], 16;" :: "r"(s), "l"(g))
#define CP_COMMIT()  asm volatile("cp.async.commit_group;" ::: "memory")
#define CP_WAIT0()   asm volatile("cp.async.wait_group 0;" ::: "memory")
#define CP_WAIT1()   asm volatile("cp.async.wait_group 1;" ::: "memory")

__device__ __forceinline__ void ldsm_x4(uint32_t r[4], uint32_t addr) {
    asm volatile("ldmatrix.sync.aligned.m8n8.x4.shared.b16 {%0,%1,%2,%3}, [%4];"
        : "=r"(r[0]), "=r"(r[1]), "=r"(r[2]), "=r"(r[3]) : "r"(addr));
}
__device__ __forceinline__ void ldsm_x2(uint32_t r[2], uint32_t addr) {
    asm volatile("ldmatrix.sync.aligned.m8n8.x2.shared.b16 {%0,%1}, [%2];"
        : "=r"(r[0]), "=r"(r[1]) : "r"(addr));
}
__device__ __forceinline__ void mma_bf16(float c[4], const uint32_t a[4],
                                         const uint32_t b[2]) {
    asm volatile(
        "mma.sync.aligned.m16n8k16.row.col.f32.bf16.bf16.f32 "
        "{%0,%1,%2,%3}, {%4,%5,%6,%7}, {%8,%9}, {%0,%1,%2,%3};"
        : "+f"(c[0]), "+f"(c[1]), "+f"(c[2]), "+f"(c[3])
        : "r"(a[0]), "r"(a[1]), "r"(a[2]), "r"(a[3]), "r"(b[0]), "r"(b[1]));
}

// ---------------------------------------------------------------------------
// GEMM1: fp32 SIMT, double-buffered smem with register prefetch.
// C[M,N] = A[M,K] * B[K,N] + bias.  128x128 tile, BK=8, 256 thr, 8x8 micro.
// ---------------------------------------------------------------------------
template<int KDIM>
__global__ __launch_bounds__(256, 2)
void sgemm128(const float* __restrict__ A, const float* __restrict__ Bm,
              const float* __restrict__ bias, float* __restrict__ C, int N)
{
    constexpr int BM = 128, BN = 128, BK = 8, TM = 8, TN = 8;
    __shared__ float As[2][BK * BM];
    __shared__ float Bs[2][BK * BN];

    const int tid  = threadIdx.x;
    const int crow = blockIdx.y * BM;
    const int ccol = blockIdx.x * BN;

    A  += (size_t)crow * KDIM;
    Bm += ccol;
    C  += (size_t)crow * N + ccol;

    const int iRA = tid >> 1;            // 0..127
    const int iCA = (tid & 1) * 4;       // 0 or 4
    const int iRB = tid >> 5;            // 0..7
    const int iCB = (tid & 31) * 4;      // 0..124

    const int tRow = (tid >> 4) * TM;
    const int tCol = (tid & 15) * TN;

    float acc[TM][TN] = {};
    float rM[TM], rN[TN];

    // prologue: load tile 0 into buffer 0
    float4 aReg = *reinterpret_cast<const float4*>(&A[(size_t)iRA * KDIM + iCA]);
    float4 bReg = *reinterpret_cast<const float4*>(&Bm[(size_t)iRB * N + iCB]);
    As[0][(iCA + 0) * BM + iRA] = aReg.x;
    As[0][(iCA + 1) * BM + iRA] = aReg.y;
    As[0][(iCA + 2) * BM + iRA] = aReg.z;
    As[0][(iCA + 3) * BM + iRA] = aReg.w;
    *reinterpret_cast<float4*>(&Bs[0][iRB * BN + iCB]) = bReg;
    __syncthreads();

    constexpr int NT = KDIM / BK;
#pragma unroll 1
    for (int it = 0; it < NT; ++it) {
        const int buf = it & 1;
        const bool more = (it + 1 < NT);
        if (more) {
            int k0 = (it + 1) * BK;
            aReg = *reinterpret_cast<const float4*>(&A[(size_t)iRA * KDIM + k0 + iCA]);
            bReg = *reinterpret_cast<const float4*>(&Bm[(size_t)(k0 + iRB) * N + iCB]);
        }
#pragma unroll
        for (int k = 0; k < BK; ++k) {
#pragma unroll
            for (int i = 0; i < TM; i += 4) {
                float4 m4 = *reinterpret_cast<const float4*>(&As[buf][k * BM + tRow + i]);
                rM[i + 0] = m4.x; rM[i + 1] = m4.y;
                rM[i + 2] = m4.z; rM[i + 3] = m4.w;
            }
#pragma unroll
            for (int j = 0; j < TN; j += 4) {
                float4 n4 = *reinterpret_cast<const float4*>(&Bs[buf][k * BN + tCol + j]);
                rN[j + 0] = n4.x; rN[j + 1] = n4.y;
                rN[j + 2] = n4.z; rN[j + 3] = n4.w;
            }
#pragma unroll
            for (int i = 0; i < TM; ++i)
#pragma unroll
                for (int j = 0; j < TN; ++j)
                    acc[i][j] = fmaf(rM[i], rN[j], acc[i][j]);
        }
        if (more) {
            const int nb = buf ^ 1;
            As[nb][(iCA + 0) * BM + iRA] = aReg.x;
            As[nb][(iCA + 1) * BM + iRA] = aReg.y;
            As[nb][(iCA + 2) * BM + iRA] = aReg.z;
            As[nb][(iCA + 3) * BM + iRA] = aReg.w;
            *reinterpret_cast<float4*>(&Bs[nb][iRB * BN + iCB]) = bReg;
        }
        __syncthreads();
    }

#pragma unroll
    for (int i = 0; i < TM; ++i) {
#pragma unroll
        for (int j = 0; j < TN; j += 4) {
            float4 v;
            v.x = acc[i][j + 0] + bias[ccol + tCol + j + 0];
            v.y = acc[i][j + 1] + bias[ccol + tCol + j + 1];
            v.z = acc[i][j + 2] + bias[ccol + tCol + j + 2];
            v.w = acc[i][j + 3] + bias[ccol + tCol + j + 3];
            *reinterpret_cast<float4*>(&C[(size_t)(tRow + i) * N + tCol + j]) = v;
        }
    }
}

// ---------------------------------------------------------------------------
// W_out[K=2048][N=1024] fp32 -> Wo1/Wo2 [N][K] bf16 2-way split
// ---------------------------------------------------------------------------
__global__ void transpose_split2(const float* __restrict__ W, int K, int N,
                                 __nv_bfloat16* __restrict__ o1,
                                 __nv_bfloat16* __restrict__ o2)
{
    __shared__ float t[32][33];
    int n0 = blockIdx.x * 32, k0 = blockIdx.y * 32;
    int tx = threadIdx.x, ty = threadIdx.y;   // (32, 8)
#pragma unroll
    for (int i = 0; i < 4; ++i)
        t[ty + i * 8][tx] = W[(size_t)(k0 + ty + i * 8) * N + n0 + tx];
    __syncthreads();
#pragma unroll
    for (int i = 0; i < 4; ++i) {
        int nn = n0 + ty + i * 8, k = k0 + tx;
        float w = t[tx][ty + i * 8];
        __nv_bfloat16 a = __float2bfloat16(w);
        float r = w - __bfloat162float(a);
        o1[(size_t)nn * K + k] = a;
        o2[(size_t)nn * K + k] = __float2bfloat16(r);
    }
}

// ---------------------------------------------------------------------------
// Hysteresis scan (fp32, identical numerics to R1). Emits split comb:
//   c1[b,t,:] = [bf16(v), bf16(s)] (2048 wide), c2v[b,t,:] = bf16(v - bf16(v))
// ---------------------------------------------------------------------------
__global__ void hsru_scan(const float* __restrict__ leak_tau,
                          const float* __restrict__ thr_arr)
{
    const int h = blockIdx.x * blockDim.x + threadIdx.x;
    const int b = blockIdx.y;
    const float alpha = 1.0f / (1.0f + expf(leak_tau[h]));
    const float th = thr_arr[h];

    float v = 0.0f, s = -1.0f;
    const float* Ip = g_I + (size_t)b * Ssz * Hsz + h;
    __nv_bfloat16* c1 = g_c1 + (size_t)b * Ssz * 2 * Hsz + h;
    __nv_bfloat16* c2 = g_c2v + (size_t)b * Ssz * Hsz + h;

    float Inext = Ip[0];
    for (int t = 0; t < Ssz; ++t) {
        float I = Inext;
        if (t + 1 < Ssz) Inext = Ip[(size_t)(t + 1) * Hsz];
        v = fmaf(alpha, v, I);
        s = (v > th) ? 1.0f : ((v < -th) ? -1.0f : s);
        __nv_bfloat16 v1 = __float2bfloat16(v);
        c1[(size_t)t * 2 * Hsz]       = v1;
        c1[(size_t)t * 2 * Hsz + Hsz] = __float2bfloat16(s);
        c2[(size_t)t * Hsz]           = __float2bfloat16(v - __bfloat162float(v1));
    }
}

// ---------------------------------------------------------------------------
// GEMM2 on mma.sync: out = tanh( c1@Wo1^T + c1@Wo2^T + c2v@Wo1[:,:1024]^T + b )
// Phase schedule (K-iters of 64): [0,32) ph0, [32,64) ph1, [64,80) ph2.
// CTA 128x128, 8 warps (2x4), warp tile 64x32, m16n8k16, register acc.
// ---------------------------------------------------------------------------
__global__ __launch_bounds__(256, 2)
void gemm2_mma(const __nv_bfloat16* __restrict__ c1,
               const __nv_bfloat16* __restrict__ c2v,
               const __nv_bfloat16* __restrict__ Wo1,
               const __nv_bfloat16* __restrict__ Wo2,
               const float* __restrict__ bias, float* __restrict__ C)
{
    extern __shared__ __align__(1024) char smem[];
    const uint32_t sb = smem_u32(smem);
    const int tid = threadIdx.x, lane = tid & 31, wid = tid >> 5;
    const int wm = wid >> 2, wn = wid & 3;
    const int m0 = blockIdx.y * 128, n0 = blockIdx.x * 128;
    constexpr int T = 80;

    float acc[4][4][4];
#pragma unroll
    for (int i = 0; i < 4; ++i)
#pragma unroll
        for (int j = 0; j < 4; ++j)
#pragma unroll
            for (int k = 0; k < 4; ++k) acc[i][j][k] = 0.0f;

    auto issue_loads = [&](int it) {
        const __nv_bfloat16* Ap; const __nv_bfloat16* Bp;
        int lda, kt;
        if (it < 32)      { Ap = c1;  lda = 2048; Bp = Wo1; kt = it * 64; }
        else if (it < 64) { Ap = c1;  lda = 2048; Bp = Wo2; kt = (it - 32) * 64; }
        else              { Ap = c2v; lda = 1024; Bp = Wo1; kt = (it - 64) * 64; }
        const int buf = it & 1;
        const uint32_t sA = sb + buf * 32768;
        const uint32_t sB = sA + 16384;
        const char* Apc = (const char*)Ap;
        const char* Bpc = (const char*)Bp;
#pragma unroll
        for (int i = 0; i < 4; ++i) {
            int id = tid + 256 * i;
            int r = id >> 3, cb = (id & 7) * 16;
            CP_ASYNC16(sA + SWZ128(r * 128 + cb),
                       Apc + ((size_t)(m0 + r) * lda + kt) * 2 + cb);
            CP_ASYNC16(sB + SWZ128(r * 128 + cb),
                       Bpc + ((size_t)(n0 + r) * 2048 + kt) * 2 + cb);
        }
    };

    issue_loads(0);
    CP_COMMIT();

#pragma unroll 1
    for (int it = 0; it < T; ++it) {
        const int buf = it & 1;
        if (it + 1 < T) { issue_loads(it + 1); CP_COMMIT(); CP_WAIT1(); }
        else            { CP_WAIT0(); }
        __syncthreads();

        const uint32_t sA = sb + buf * 32768;
        const uint32_t sB = sA + 16384;
#pragma unroll
        for (int kk = 0; kk < 4; ++kk) {
            uint32_t aF[4][4], bF[4][2];
#pragma unroll
            for (int mt = 0; mt < 4; ++mt) {
                int row = wm * 64 + mt * 16 + (lane & 15);
                int colb = kk * 32 + (lane >> 4) * 16;
                ldsm_x4(aF[mt], sA + SWZ128(row * 128 + colb));
            }
#pragma unroll
            for (int nt = 0; nt < 4; ++nt) {
                int row = wn * 32 + nt * 8 + (lane & 7);
                int colb = kk * 32 + ((lane >> 3) & 1) * 16;
                ldsm_x2(bF[nt], sB + SWZ128(row * 128 + colb));
            }
#pragma unroll
            for (int mt = 0; mt < 4; ++mt)
#pragma unroll
                for (int nt = 0; nt < 4; ++nt)
                    mma_bf16(acc[mt][nt], aF[mt], bF[nt]);
        }
        __syncthreads();
    }

    // Epilogue: bias + tanh, float2 stores
    const int gid = lane >> 2, tig = lane & 3;
#pragma unroll
    for (int mt = 0; mt < 4; ++mt) {
#pragma unroll
        for (int nt = 0; nt < 4; ++nt) {
            int col = n0 + wn * 32 + nt * 8 + 2 * tig;
            float2 bv = *reinterpret_cast<const float2*>(&bias[col]);
            int r0 = m0 + wm * 64 + mt * 16 + gid;
            float2 v0, v1;
            v0.x = tanhf(acc[mt][nt][0] + bv.x);
            v0.y = tanhf(acc[mt][nt][1] + bv.y);
            v1.x = tanhf(acc[mt][nt][2] + bv.x);
            v1.y = tanhf(acc[mt][nt][3] + bv.y);
            *reinterpret_cast<float2*>(&C[(size_t)r0 * NG + col]) = v0;
            *reinterpret_cast<float2*>(&C[(size_t)(r0 + 8) * NG + col]) = v1;
        }
    }
}

// ---------------------------------------------------------------------------
extern "C" void kernel_launch(void* const* d_in, const int* in_sizes, int n_in,
                              void* d_out, int out_size)
{
    const float* x        = (const float*)d_in[0];
    const float* W_in     = (const float*)d_in[1];
    const float* b_in     = (const float*)d_in[2];
    const float* leak_tau = (const float*)d_in[3];
    const float* thr      = (const float*)d_in[4];
    const float* W_out    = (const float*)d_in[5];
    const float* b_out    = (const float*)d_in[6];
    float* out = (float*)d_out;

    float* pI; cudaGetSymbolAddress((void**)&pI, g_I);
    __nv_bfloat16 *c1, *c2v, *Wo1, *Wo2;
    cudaGetSymbolAddress((void**)&c1,  g_c1);
    cudaGetSymbolAddress((void**)&c2v, g_c2v);
    cudaGetSymbolAddress((void**)&Wo1, g_Wo1);
    cudaGetSymbolAddress((void**)&Wo2, g_Wo2);

    cudaFuncSetAttribute(gemm2_mma,
                         cudaFuncAttributeMaxDynamicSharedMemorySize, GEMM2_SMEM);

    // W_out split (overlappable with GEMM1 on the same stream order-wise)
    transpose_split2<<<dim3(Hsz / 32, (2 * Hsz) / 32), dim3(32, 8)>>>(
        W_out, 2 * Hsz, Hsz, Wo1, Wo2);

    // GEMM1: I = x @ W_in + b_in  (fp32, exact-as-R1 numerics)
    sgemm128<INsz><<<dim3(Hsz / 128, Msz / 128), 256>>>(x, W_in, b_in, pI, Hsz);

    // Scan -> c1, c2v
    hsru_scan<<<dim3(Hsz / 256, Bsz), 256>>>(leak_tau, thr);

    // GEMM2: out = tanh(comb @ W_out + b_out) via 3-term bf16 split
    gemm2_mma<<<dim3(NG / 128, Msz / 128), 256, GEMM2_SMEM>>>(
        c1, c2v, Wo1, Wo2, b_out, out);
}

// round 7
// speedup vs baseline: 2.1712x; 1.1380x over previous
#include <cuda_runtime.h>
#include <cuda_bf16.h>
#include <stdint.h>
#include <math.h>

// ---------------------------------------------------------------------------
// Problem dims
// ---------------------------------------------------------------------------
namespace {
constexpr int Bsz  = 16;
constexpr int Ssz  = 2048;
constexpr int Hsz  = 1024;
constexpr int INsz = 1024;
constexpr int Msz  = Bsz * Ssz;       // 32768
constexpr int NG   = 1024;
constexpr int STAGE_BYTES = 32768;    // 16KB A + 16KB B per stage
constexpr int GEMM_SMEM = 3 * STAGE_BYTES;  // 96 KiB, 3-stage ring
}

// ---------------------------------------------------------------------------
// Scratch (__device__ globals; no allocation allowed)
// ---------------------------------------------------------------------------
__device__ float g_I[(size_t)Msz * Hsz];                   // 128 MiB
__device__ __nv_bfloat16 g_xa[(size_t)Msz * INsz];         // x 3-way split
__device__ __nv_bfloat16 g_xb[(size_t)Msz * INsz];
__device__ __nv_bfloat16 g_xc[(size_t)Msz * INsz];
__device__ __nv_bfloat16 g_c1[(size_t)Msz * 2 * Hsz];      // [M][2048]: v | s
__device__ __nv_bfloat16 g_c2v[(size_t)Msz * Hsz];         // [M][1024]: v residual
__device__ __nv_bfloat16 g_Wi1[(size_t)Hsz * INsz];        // W_in^T splits [N][K]
__device__ __nv_bfloat16 g_Wi2[(size_t)Hsz * INsz];
__device__ __nv_bfloat16 g_Wi3[(size_t)Hsz * INsz];
__device__ __nv_bfloat16 g_Wo1[(size_t)Hsz * 2 * Hsz];     // W_out^T splits [N][2048]
__device__ __nv_bfloat16 g_Wo2[(size_t)Hsz * 2 * Hsz];

// ---------------------------------------------------------------------------
// PTX helpers (base sm_80+ features only)
// ---------------------------------------------------------------------------
#define SWZ128(o) ((o) ^ (((o) >> 3) & 0x70))

__device__ __forceinline__ uint32_t smem_u32(const void* p) {
    uint32_t a;
    asm("{ .reg .u64 t; cvta.to.shared.u64 t, %1; cvt.u32.u64 %0, t; }"
        : "=r"(a) : "l"(p));
    return a;
}
#define CP_ASYNC16(s, g) \
    asm volatile("cp.async.cg.shared.global [%0], [%1], 16;" :: "r"(s), "l"(g))
#define CP_COMMIT()  asm volatile("cp.async.commit_group;" ::: "memory")
#define CP_WAIT0()   asm volatile("cp.async.wait_group 0;" ::: "memory")
#define CP_WAIT1()   asm volatile("cp.async.wait_group 1;" ::: "memory")

__device__ __forceinline__ void ldsm_x4(uint32_t r[4], uint32_t addr) {
    asm volatile("ldmatrix.sync.aligned.m8n8.x4.shared.b16 {%0,%1,%2,%3}, [%4];"
        : "=r"(r[0]), "=r"(r[1]), "=r"(r[2]), "=r"(r[3]) : "r"(addr));
}
__device__ __forceinline__ void ldsm_x2(uint32_t r[2], uint32_t addr) {
    asm volatile("ldmatrix.sync.aligned.m8n8.x2.shared.b16 {%0,%1}, [%2];"
        : "=r"(r[0]), "=r"(r[1]) : "r"(addr));
}
__device__ __forceinline__ void mma_bf16(float c[4], const uint32_t a[4],
                                         const uint32_t b[2]) {
    asm volatile(
        "mma.sync.aligned.m16n8k16.row.col.f32.bf16.bf16.f32 "
        "{%0,%1,%2,%3}, {%4,%5,%6,%7}, {%8,%9}, {%0,%1,%2,%3};"
        : "+f"(c[0]), "+f"(c[1]), "+f"(c[2]), "+f"(c[3])
        : "r"(a[0]), "r"(a[1]), "r"(a[2]), "r"(a[3]), "r"(b[0]), "r"(b[1]));
}

// ---------------------------------------------------------------------------
// Split kernels
// ---------------------------------------------------------------------------
__global__ void split3_x(const float* __restrict__ x, __nv_bfloat16* __restrict__ o1,
                         __nv_bfloat16* __restrict__ o2, __nv_bfloat16* __restrict__ o3,
                         size_t n)
{
    size_t i = (size_t)blockIdx.x * blockDim.x + threadIdx.x;
    size_t stride = (size_t)gridDim.x * blockDim.x;
    for (; i < n; i += stride) {
        float w = x[i];
        __nv_bfloat16 a = __float2bfloat16(w);
        float r = w - __bfloat162float(a);
        __nv_bfloat16 b = __float2bfloat16(r);
        float r2 = r - __bfloat162float(b);
        o1[i] = a; o2[i] = b; o3[i] = __float2bfloat16(r2);
    }
}

// W[K][N] fp32 -> o[N][K] bf16 splits (o3 optional)
__global__ void transpose_split(const float* __restrict__ W, int K, int N,
                                __nv_bfloat16* __restrict__ o1,
                                __nv_bfloat16* __restrict__ o2,
                                __nv_bfloat16* __restrict__ o3)
{
    __shared__ float t[32][33];
    int n0 = blockIdx.x * 32, k0 = blockIdx.y * 32;
    int tx = threadIdx.x, ty = threadIdx.y;   // (32, 8)
#pragma unroll
    for (int i = 0; i < 4; ++i)
        t[ty + i * 8][tx] = W[(size_t)(k0 + ty + i * 8) * N + n0 + tx];
    __syncthreads();
#pragma unroll
    for (int i = 0; i < 4; ++i) {
        int nn = n0 + ty + i * 8, k = k0 + tx;
        float w = t[tx][ty + i * 8];
        __nv_bfloat16 a = __float2bfloat16(w);
        float r = w - __bfloat162float(a);
        __nv_bfloat16 b = __float2bfloat16(r);
        o1[(size_t)nn * K + k] = a;
        o2[(size_t)nn * K + k] = b;
        if (o3) {
            float r2 = r - __bfloat162float(b);
            o3[(size_t)nn * K + k] = __float2bfloat16(r2);
        }
    }
}

// ---------------------------------------------------------------------------
// Hysteresis scan (fp32). Emits split comb:
//   c1[b,t,:] = [bf16(v), bf16(s)] (2048 wide), c2v[b,t,:] = bf16(v - bf16(v))
// ---------------------------------------------------------------------------
__global__ void hsru_scan(const float* __restrict__ leak_tau,
                          const float* __restrict__ thr_arr)
{
    const int h = blockIdx.x * blockDim.x + threadIdx.x;
    const int b = blockIdx.y;
    const float alpha = 1.0f / (1.0f + expf(leak_tau[h]));
    const float th = thr_arr[h];

    float v = 0.0f, s = -1.0f;
    const float* Ip = g_I + (size_t)b * Ssz * Hsz + h;
    __nv_bfloat16* c1 = g_c1 + (size_t)b * Ssz * 2 * Hsz + h;
    __nv_bfloat16* c2 = g_c2v + (size_t)b * Ssz * Hsz + h;

    float Inext = Ip[0];
    for (int t = 0; t < Ssz; ++t) {
        float I = Inext;
        if (t + 1 < Ssz) Inext = Ip[(size_t)(t + 1) * Hsz];
        v = fmaf(alpha, v, I);
        s = (v > th) ? 1.0f : ((v < -th) ? -1.0f : s);
        __nv_bfloat16 v1 = __float2bfloat16(v);
        c1[(size_t)t * 2 * Hsz]       = v1;
        c1[(size_t)t * 2 * Hsz + Hsz] = __float2bfloat16(s);
        c2[(size_t)t * Hsz]           = __float2bfloat16(v - __bfloat162float(v1));
    }
}

// ---------------------------------------------------------------------------
// Multi-phase bf16 split-GEMM on mma.sync.
// C[M,NG] = sum_ph A_ph[M,K_ph] @ B_ph[NG,K_ph]^T (+bias, opt tanh)
// CTA 128x128, BK=64, 8 warps (2x4), warp tile 64x32, m16n8k16.
// 3-stage cp.async ring, ONE __syncthreads per K-iter.
// RACE-SAFE ORDER: wait(stage it) -> barrier -> issue(it+2) -> compute(it).
//   The barrier certifies all warps finished compute(it-1) before anyone
//   overwrites stage (it+2)%3 == (it-1)%3.
// Registers accumulate across all phases; phase order = small terms first.
// ---------------------------------------------------------------------------
struct GemmSpec {
    const __nv_bfloat16* A[6];
    const __nv_bfloat16* B[6];
    int lda[6];        // A row stride (elements)
    int ldb[6];        // B row stride (elements)
    int cum[7];        // cumulative K-iterations (64 each) per phase
};

template<int NPH, int T, bool DO_TANH>
__global__ __launch_bounds__(256, 2)
void gemm_mma(const __grid_constant__ GemmSpec spec,
              const float* __restrict__ bias, float* __restrict__ C)
{
    extern __shared__ __align__(1024) char smem[];
    const uint32_t sb = smem_u32(smem);
    const int tid = threadIdx.x, lane = tid & 31, wid = tid >> 5;
    const int wm = wid >> 2, wn = wid & 3;          // warp grid 2 (M) x 4 (N)
    const int m0 = blockIdx.y * 128, n0 = blockIdx.x * 128;

    float acc[4][4][4];
#pragma unroll
    for (int i = 0; i < 4; ++i)
#pragma unroll
        for (int j = 0; j < 4; ++j)
#pragma unroll
            for (int k = 0; k < 4; ++k) acc[i][j][k] = 0.0f;

    auto issue_loads = [&](int it) {
        int ph = 0;
#pragma unroll
        for (int p = 0; p < NPH - 1; ++p) if (it >= spec.cum[p + 1]) ph = p + 1;
        const int kt = (it - spec.cum[ph]) * 64;
        const int lda = spec.lda[ph], ldb = spec.ldb[ph];
        const char* Apc = (const char*)spec.A[ph];
        const char* Bpc = (const char*)spec.B[ph];
        const uint32_t sA = sb + (it % 3) * STAGE_BYTES;
        const uint32_t sB = sA + 16384;
#pragma unroll
        for (int i = 0; i < 4; ++i) {
            int id = tid + 256 * i;
            int r = id >> 3, cb = (id & 7) * 16;
            CP_ASYNC16(sA + SWZ128(r * 128 + cb),
                       Apc + ((size_t)(m0 + r) * lda + kt) * 2 + cb);
            CP_ASYNC16(sB + SWZ128(r * 128 + cb),
                       Bpc + ((size_t)(n0 + r) * ldb + kt) * 2 + cb);
        }
    };

    issue_loads(0); CP_COMMIT();
    issue_loads(1); CP_COMMIT();

#pragma unroll 1
    for (int it = 0; it < T; ++it) {
        // Retire group for stage 'it' (pending: G_it, G_{it+1} at most)
        if (it + 1 < T) { CP_WAIT1(); } else { CP_WAIT0(); }
        __syncthreads();             // compute(it-1) done everywhere; stage it visible
        if (it + 2 < T) { issue_loads(it + 2); CP_COMMIT(); }

        const uint32_t sA = sb + (it % 3) * STAGE_BYTES;
        const uint32_t sB = sA + 16384;
#pragma unroll
        for (int kk = 0; kk < 4; ++kk) {
            uint32_t aF[4][4], bF[4][2];
#pragma unroll
            for (int mt = 0; mt < 4; ++mt) {
                int row = wm * 64 + mt * 16 + (lane & 15);
                int colb = kk * 32 + (lane >> 4) * 16;
                ldsm_x4(aF[mt], sA + SWZ128(row * 128 + colb));
            }
#pragma unroll
            for (int nt = 0; nt < 4; ++nt) {
                int row = wn * 32 + nt * 8 + (lane & 7);
                int colb = kk * 32 + ((lane >> 3) & 1) * 16;
                ldsm_x2(bF[nt], sB + SWZ128(row * 128 + colb));
            }
#pragma unroll
            for (int mt = 0; mt < 4; ++mt)
#pragma unroll
                for (int nt = 0; nt < 4; ++nt)
                    mma_bf16(acc[mt][nt], aF[mt], bF[nt]);
        }
    }

    // Epilogue: bias (+tanh), float2 stores straight from fragments
    const int gid = lane >> 2, tig = lane & 3;
#pragma unroll
    for (int mt = 0; mt < 4; ++mt) {
#pragma unroll
        for (int nt = 0; nt < 4; ++nt) {
            int col = n0 + wn * 32 + nt * 8 + 2 * tig;
            float2 bv = *reinterpret_cast<const float2*>(&bias[col]);
            int r0 = m0 + wm * 64 + mt * 16 + gid;
            float2 v0, v1;
            v0.x = acc[mt][nt][0] + bv.x; v0.y = acc[mt][nt][1] + bv.y;
            v1.x = acc[mt][nt][2] + bv.x; v1.y = acc[mt][nt][3] + bv.y;
            if (DO_TANH) {
                v0.x = tanhf(v0.x); v0.y = tanhf(v0.y);
                v1.x = tanhf(v1.x); v1.y = tanhf(v1.y);
            }
            *reinterpret_cast<float2*>(&C[(size_t)r0 * NG + col]) = v0;
            *reinterpret_cast<float2*>(&C[(size_t)(r0 + 8) * NG + col]) = v1;
        }
    }
}

// ---------------------------------------------------------------------------
extern "C" void kernel_launch(void* const* d_in, const int* in_sizes, int n_in,
                              void* d_out, int out_size)
{
    const float* x        = (const float*)d_in[0];
    const float* W_in     = (const float*)d_in[1];
    const float* b_in     = (const float*)d_in[2];
    const float* leak_tau = (const float*)d_in[3];
    const float* thr      = (const float*)d_in[4];
    const float* W_out    = (const float*)d_in[5];
    const float* b_out    = (const float*)d_in[6];
    float* out = (float*)d_out;

    float* pI; cudaGetSymbolAddress((void**)&pI, g_I);
    __nv_bfloat16 *xa, *xb, *xc, *c1, *c2v, *Wi1, *Wi2, *Wi3, *Wo1, *Wo2;
    cudaGetSymbolAddress((void**)&xa,  g_xa);
    cudaGetSymbolAddress((void**)&xb,  g_xb);
    cudaGetSymbolAddress((void**)&xc,  g_xc);
    cudaGetSymbolAddress((void**)&c1,  g_c1);
    cudaGetSymbolAddress((void**)&c2v, g_c2v);
    cudaGetSymbolAddress((void**)&Wi1, g_Wi1);
    cudaGetSymbolAddress((void**)&Wi2, g_Wi2);
    cudaGetSymbolAddress((void**)&Wi3, g_Wi3);
    cudaGetSymbolAddress((void**)&Wo1, g_Wo1);
    cudaGetSymbolAddress((void**)&Wo2, g_Wo2);

    cudaFuncSetAttribute(gemm_mma<6, 96, false>,
                         cudaFuncAttributeMaxDynamicSharedMemorySize, GEMM_SMEM);
    cudaFuncSetAttribute(gemm_mma<3, 80, true>,
                         cudaFuncAttributeMaxDynamicSharedMemorySize, GEMM_SMEM);

    // Splits
    split3_x<<<2048, 256>>>(x, xa, xb, xc, (size_t)Msz * INsz);
    transpose_split<<<dim3(Hsz / 32, INsz / 32), dim3(32, 8)>>>(
        W_in, INsz, Hsz, Wi1, Wi2, Wi3);
    transpose_split<<<dim3(Hsz / 32, (2 * Hsz) / 32), dim3(32, 8)>>>(
        W_out, 2 * Hsz, Hsz, Wo1, Wo2, nullptr);

    // GEMM1: I = x @ W_in + b_in — 6-term split, SMALL TERMS FIRST, (1,1) LAST
    {
        GemmSpec g = {};
        const __nv_bfloat16* As[6] = { xb,  xa,  xb,  xc,  xa,  xa  };
        const __nv_bfloat16* Bs[6] = { Wi1, Wi2, Wi2, Wi1, Wi3, Wi1 };
        for (int p = 0; p < 6; ++p) {
            g.A[p] = As[p]; g.B[p] = Bs[p];
            g.lda[p] = INsz; g.ldb[p] = INsz;
            g.cum[p] = p * 16;
        }
        g.cum[6] = 96;
        gemm_mma<6, 96, false><<<dim3(Hsz / 128, Msz / 128), 256, GEMM_SMEM>>>(
            g, b_in, pI);
    }

    // Scan -> c1, c2v
    hsru_scan<<<dim3(Hsz / 256, Bsz), 256>>>(leak_tau, thr);

    // GEMM2: out = tanh(comb @ W_out + b_out) — (1,2), (2,1), then (1,1) last
    {
        GemmSpec g = {};
        g.A[0] = c1;  g.B[0] = Wo2; g.lda[0] = 2048; g.ldb[0] = 2048;
        g.A[1] = c2v; g.B[1] = Wo1; g.lda[1] = 1024; g.ldb[1] = 2048;
        g.A[2] = c1;  g.B[2] = Wo1; g.lda[2] = 2048; g.ldb[2] = 2048;
        g.cum[0] = 0; g.cum[1] = 32; g.cum[2] = 48; g.cum[3] = 80;
        for (int p = 3; p < 6; ++p) { g.A[p] = c1; g.B[p] = Wo1; g.lda[p] = 2048; g.ldb[p] = 2048; }
        g.cum[4] = g.cum[5] = g.cum[6] = 80;
        gemm_mma<3, 80, true><<<dim3(NG / 128, Msz / 128), 256, GEMM_SMEM>>>(
            g, b_out, out);
    }
}

// round 8
// speedup vs baseline: 2.6161x; 1.2049x over previous
#include <cuda_runtime.h>
#include <cuda_bf16.h>
#include <stdint.h>
#include <math.h>

// ---------------------------------------------------------------------------
// Problem dims
// ---------------------------------------------------------------------------
namespace {
constexpr int Bsz  = 16;
constexpr int Ssz  = 2048;
constexpr int Hsz  = 1024;
constexpr int INsz = 1024;
constexpr int Msz  = Bsz * Ssz;       // 32768
constexpr int NG   = 1024;
constexpr int STAGE_BYTES = 32768;    // 16KB A + 16KB B per stage
constexpr int GEMM_SMEM = 3 * STAGE_BYTES;  // 96 KiB, 3-stage ring
constexpr int NC   = 32;              // scan chunks
constexpr int CL   = Ssz / NC;        // 64 timesteps per chunk
}

// ---------------------------------------------------------------------------
// Scratch (__device__ globals; no allocation allowed)
// ---------------------------------------------------------------------------
__device__ float g_I[(size_t)Msz * Hsz];                   // 128 MiB
__device__ __nv_bfloat16 g_xa[(size_t)Msz * INsz];         // x 3-way split
__device__ __nv_bfloat16 g_xb[(size_t)Msz * INsz];
__device__ __nv_bfloat16 g_xc[(size_t)Msz * INsz];
__device__ __nv_bfloat16 g_c1[(size_t)Msz * 2 * Hsz];      // [M][2048]: v | s
__device__ __nv_bfloat16 g_c2v[(size_t)Msz * Hsz];         // [M][1024]: v residual
__device__ __nv_bfloat16 g_Wi1[(size_t)Hsz * INsz];        // W_in^T splits [N][K]
__device__ __nv_bfloat16 g_Wi2[(size_t)Hsz * INsz];
__device__ __nv_bfloat16 g_Wi3[(size_t)Hsz * INsz];
__device__ __nv_bfloat16 g_Wo1[(size_t)Hsz * 2 * Hsz];     // W_out^T splits [N][2048]
__device__ __nv_bfloat16 g_Wo2[(size_t)Hsz * 2 * Hsz];
// scan pipeline scratch: [c][b][h]
__device__ float g_vend [(size_t)NC * Bsz * Hsz];
__device__ float g_vinit[(size_t)NC * Bsz * Hsz];
__device__ int   g_fc   [(size_t)NC * Bsz * Hsz];          // first crossing (local idx, CL if none)
__device__ float g_ls   [(size_t)NC * Bsz * Hsz];          // last crossing sign
__device__ float g_sinit[(size_t)NC * Bsz * Hsz];          // s at chunk start

// ---------------------------------------------------------------------------
// PTX helpers (base sm_80+ features only)
// ---------------------------------------------------------------------------
#define SWZ128(o) ((o) ^ (((o) >> 3) & 0x70))

__device__ __forceinline__ uint32_t smem_u32(const void* p) {
    uint32_t a;
    asm("{ .reg .u64 t; cvta.to.shared.u64 t, %1; cvt.u32.u64 %0, t; }"
        : "=r"(a) : "l"(p));
    return a;
}
#define CP_ASYNC16(s, g) \
    asm volatile("cp.async.cg.shared.global [%0], [%1], 16;" :: "r"(s), "l"(g))
#define CP_COMMIT()  asm volatile("cp.async.commit_group;" ::: "memory")
#define CP_WAIT0()   asm volatile("cp.async.wait_group 0;" ::: "memory")
#define CP_WAIT1()   asm volatile("cp.async.wait_group 1;" ::: "memory")

__device__ __forceinline__ void ldsm_x4(uint32_t r[4], uint32_t addr) {
    asm volatile("ldmatrix.sync.aligned.m8n8.x4.shared.b16 {%0,%1,%2,%3}, [%4];"
        : "=r"(r[0]), "=r"(r[1]), "=r"(r[2]), "=r"(r[3]) : "r"(addr));
}
__device__ __forceinline__ void ldsm_x2(uint32_t r[2], uint32_t addr) {
    asm volatile("ldmatrix.sync.aligned.m8n8.x2.shared.b16 {%0,%1}, [%2];"
        : "=r"(r[0]), "=r"(r[1]) : "r"(addr));
}
__device__ __forceinline__ void mma_bf16(float c[4], const uint32_t a[4],
                                         const uint32_t b[2]) {
    asm volatile(
        "mma.sync.aligned.m16n8k16.row.col.f32.bf16.bf16.f32 "
        "{%0,%1,%2,%3}, {%4,%5,%6,%7}, {%8,%9}, {%0,%1,%2,%3};"
        : "+f"(c[0]), "+f"(c[1]), "+f"(c[2]), "+f"(c[3])
        : "r"(a[0]), "r"(a[1]), "r"(a[2]), "r"(a[3]), "r"(b[0]), "r"(b[1]));
}

// ---------------------------------------------------------------------------
// Split kernels
// ---------------------------------------------------------------------------
__global__ void split3_x(const float* __restrict__ x, __nv_bfloat16* __restrict__ o1,
                         __nv_bfloat16* __restrict__ o2, __nv_bfloat16* __restrict__ o3,
                         size_t n)
{
    size_t i = (size_t)blockIdx.x * blockDim.x + threadIdx.x;
    size_t stride = (size_t)gridDim.x * blockDim.x;
    for (; i < n; i += stride) {
        float w = x[i];
        __nv_bfloat16 a = __float2bfloat16(w);
        float r = w - __bfloat162float(a);
        __nv_bfloat16 b = __float2bfloat16(r);
        float r2 = r - __bfloat162float(b);
        o1[i] = a; o2[i] = b; o3[i] = __float2bfloat16(r2);
    }
}

// W[K][N] fp32 -> o[N][K] bf16 splits (o3 optional)
__global__ void transpose_split(const float* __restrict__ W, int K, int N,
                                __nv_bfloat16* __restrict__ o1,
                                __nv_bfloat16* __restrict__ o2,
                                __nv_bfloat16* __restrict__ o3)
{
    __shared__ float t[32][33];
    int n0 = blockIdx.x * 32, k0 = blockIdx.y * 32;
    int tx = threadIdx.x, ty = threadIdx.y;   // (32, 8)
#pragma unroll
    for (int i = 0; i < 4; ++i)
        t[ty + i * 8][tx] = W[(size_t)(k0 + ty + i * 8) * N + n0 + tx];
    __syncthreads();
#pragma unroll
    for (int i = 0; i < 4; ++i) {
        int nn = n0 + ty + i * 8, k = k0 + tx;
        float w = t[tx][ty + i * 8];
        __nv_bfloat16 a = __float2bfloat16(w);
        float r = w - __bfloat162float(a);
        __nv_bfloat16 b = __float2bfloat16(r);
        o1[(size_t)nn * K + k] = a;
        o2[(size_t)nn * K + k] = b;
        if (o3) {
            float r2 = r - __bfloat162float(b);
            o3[(size_t)nn * K + k] = __float2bfloat16(r2);
        }
    }
}

// ---------------------------------------------------------------------------
// Chunked parallel hysteresis scan.
//   v is linear: v_t = alpha^(t-t0) * v_start + local_chain  (exact)
//   s is "last crossing wins" across chunks.
// Grid for per-chunk kernels: (H/256, B, NC).
// ---------------------------------------------------------------------------
__device__ __forceinline__ float sig_alpha(const float* lt, int h) {
    return 1.0f / (1.0f + expf(lt[h]));
}

// S1: local chain end value per chunk (v_init = 0)
__global__ void scan_s1(const float* __restrict__ leak_tau)
{
    const int h = blockIdx.x * blockDim.x + threadIdx.x;
    const int b = blockIdx.y, c = blockIdx.z;
    const float alpha = sig_alpha(leak_tau, h);
    const float* Ip = g_I + ((size_t)b * Ssz + c * CL) * Hsz + h;
    float v = 0.0f;
#pragma unroll 4
    for (int t = 0; t < CL; ++t)
        v = fmaf(alpha, v, Ip[(size_t)t * Hsz]);
    g_vend[((size_t)c * Bsz + b) * Hsz + h] = v;
}

// S2: sequential chunk combine -> true v at chunk starts
__global__ void scan_s2(const float* __restrict__ leak_tau)
{
    const int h = blockIdx.x * blockDim.x + threadIdx.x;
    const int b = blockIdx.y;
    const float alpha = sig_alpha(leak_tau, h);
    const float aL = powf(alpha, (float)CL);
    float v = 0.0f;
    for (int c = 0; c < NC; ++c) {
        size_t o = ((size_t)c * Bsz + b) * Hsz + h;
        g_vinit[o] = v;
        v = fmaf(aL, v, g_vend[o]);
    }
}

// S3: replay chunk with true v_init; emit v parts, s after first crossing,
//     and (first_cross, last_sign) for the s carry.
__global__ void scan_s3(const float* __restrict__ leak_tau,
                        const float* __restrict__ thr_arr)
{
    const int h = blockIdx.x * blockDim.x + threadIdx.x;
    const int b = blockIdx.y, c = blockIdx.z;
    const float alpha = sig_alpha(leak_tau, h);
    const float th = thr_arr[h];
    const size_t co = ((size_t)c * Bsz + b) * Hsz + h;
    float v = g_vinit[co];

    const int t0 = c * CL;
    const float* Ip = g_I + ((size_t)b * Ssz + t0) * Hsz + h;
    __nv_bfloat16* c1 = g_c1 + ((size_t)b * Ssz + t0) * 2 * Hsz + h;
    __nv_bfloat16* c2 = g_c2v + ((size_t)b * Ssz + t0) * Hsz + h;

    int fc = CL;
    float s = 0.0f;   // valid only after first crossing
#pragma unroll 4
    for (int t = 0; t < CL; ++t) {
        v = fmaf(alpha, v, Ip[(size_t)t * Hsz]);
        bool up = v > th, dn = v < -th;
        if (up | dn) {
            if (fc == CL) fc = t;
            s = up ? 1.0f : -1.0f;
        }
        __nv_bfloat16 v1 = __float2bfloat16(v);
        c1[(size_t)t * 2 * Hsz] = v1;
        c2[(size_t)t * Hsz]     = __float2bfloat16(v - __bfloat162float(v1));
        if (fc != CL)
            c1[(size_t)t * 2 * Hsz + Hsz] = __float2bfloat16(s);
    }
    g_fc[co] = fc;
    g_ls[co] = s;
}

// S4: sequential s-carry across chunks
__global__ void scan_s4()
{
    const int h = blockIdx.x * blockDim.x + threadIdx.x;
    const int b = blockIdx.y;
    float s = -1.0f;
    for (int c = 0; c < NC; ++c) {
        size_t o = ((size_t)c * Bsz + b) * Hsz + h;
        g_sinit[o] = s;
        if (g_fc[o] < CL) s = g_ls[o];
    }
}

// S5: fill pre-first-crossing prefix of each chunk's s-half with carried s
__global__ void scan_s5()
{
    const int h = blockIdx.x * blockDim.x + threadIdx.x;
    const int b = blockIdx.y, c = blockIdx.z;
    const size_t co = ((size_t)c * Bsz + b) * Hsz + h;
    const int fc = g_fc[co];
    if (fc == 0) return;
    const __nv_bfloat16 sv = __float2bfloat16(g_sinit[co]);
    __nv_bfloat16* c1s = g_c1 + ((size_t)b * Ssz + c * CL) * 2 * Hsz + Hsz + h;
    for (int t = 0; t < fc; ++t)
        c1s[(size_t)t * 2 * Hsz] = sv;
}

// ---------------------------------------------------------------------------
// Multi-phase bf16 split-GEMM on mma.sync (unchanged from R6 — proven).
// ---------------------------------------------------------------------------
struct GemmSpec {
    const __nv_bfloat16* A[6];
    const __nv_bfloat16* B[6];
    int lda[6];
    int ldb[6];
    int cum[7];
};

template<int NPH, int T, bool DO_TANH>
__global__ __launch_bounds__(256, 2)
void gemm_mma(const __grid_constant__ GemmSpec spec,
              const float* __restrict__ bias, float* __restrict__ C)
{
    extern __shared__ __align__(1024) char smem[];
    const uint32_t sb = smem_u32(smem);
    const int tid = threadIdx.x, lane = tid & 31, wid = tid >> 5;
    const int wm = wid >> 2, wn = wid & 3;
    const int m0 = blockIdx.y * 128, n0 = blockIdx.x * 128;

    float acc[4][4][4];
#pragma unroll
    for (int i = 0; i < 4; ++i)
#pragma unroll
        for (int j = 0; j < 4; ++j)
#pragma unroll
            for (int k = 0; k < 4; ++k) acc[i][j][k] = 0.0f;

    auto issue_loads = [&](int it) {
        int ph = 0;
#pragma unroll
        for (int p = 0; p < NPH - 1; ++p) if (it >= spec.cum[p + 1]) ph = p + 1;
        const int kt = (it - spec.cum[ph]) * 64;
        const int lda = spec.lda[ph], ldb = spec.ldb[ph];
        const char* Apc = (const char*)spec.A[ph];
        const char* Bpc = (const char*)spec.B[ph];
        const uint32_t sA = sb + (it % 3) * STAGE_BYTES;
        const uint32_t sB = sA + 16384;
#pragma unroll
        for (int i = 0; i < 4; ++i) {
            int id = tid + 256 * i;
            int r = id >> 3, cb = (id & 7) * 16;
            CP_ASYNC16(sA + SWZ128(r * 128 + cb),
                       Apc + ((size_t)(m0 + r) * lda + kt) * 2 + cb);
            CP_ASYNC16(sB + SWZ128(r * 128 + cb),
                       Bpc + ((size_t)(n0 + r) * ldb + kt) * 2 + cb);
        }
    };

    issue_loads(0); CP_COMMIT();
    issue_loads(1); CP_COMMIT();

#pragma unroll 1
    for (int it = 0; it < T; ++it) {
        if (it + 1 < T) { CP_WAIT1(); } else { CP_WAIT0(); }
        __syncthreads();
        if (it + 2 < T) { issue_loads(it + 2); CP_COMMIT(); }

        const uint32_t sA = sb + (it % 3) * STAGE_BYTES;
        const uint32_t sB = sA + 16384;
#pragma unroll
        for (int kk = 0; kk < 4; ++kk) {
            uint32_t aF[4][4], bF[4][2];
#pragma unroll
            for (int mt = 0; mt < 4; ++mt) {
                int row = wm * 64 + mt * 16 + (lane & 15);
                int colb = kk * 32 + (lane >> 4) * 16;
                ldsm_x4(aF[mt], sA + SWZ128(row * 128 + colb));
            }
#pragma unroll
            for (int nt = 0; nt < 4; ++nt) {
                int row = wn * 32 + nt * 8 + (lane & 7);
                int colb = kk * 32 + ((lane >> 3) & 1) * 16;
                ldsm_x2(bF[nt], sB + SWZ128(row * 128 + colb));
            }
#pragma unroll
            for (int mt = 0; mt < 4; ++mt)
#pragma unroll
                for (int nt = 0; nt < 4; ++nt)
                    mma_bf16(acc[mt][nt], aF[mt], bF[nt]);
        }
    }

    const int gid = lane >> 2, tig = lane & 3;
#pragma unroll
    for (int mt = 0; mt < 4; ++mt) {
#pragma unroll
        for (int nt = 0; nt < 4; ++nt) {
            int col = n0 + wn * 32 + nt * 8 + 2 * tig;
            float2 bv = *reinterpret_cast<const float2*>(&bias[col]);
            int r0 = m0 + wm * 64 + mt * 16 + gid;
            float2 v0, v1;
            v0.x = acc[mt][nt][0] + bv.x; v0.y = acc[mt][nt][1] + bv.y;
            v1.x = acc[mt][nt][2] + bv.x; v1.y = acc[mt][nt][3] + bv.y;
            if (DO_TANH) {
                v0.x = tanhf(v0.x); v0.y = tanhf(v0.y);
                v1.x = tanhf(v1.x); v1.y = tanhf(v1.y);
            }
            *reinterpret_cast<float2*>(&C[(size_t)r0 * NG + col]) = v0;
            *reinterpret_cast<float2*>(&C[(size_t)(r0 + 8) * NG + col]) = v1;
        }
    }
}

// ---------------------------------------------------------------------------
extern "C" void kernel_launch(void* const* d_in, const int* in_sizes, int n_in,
                              void* d_out, int out_size)
{
    const float* x        = (const float*)d_in[0];
    const float* W_in     = (const float*)d_in[1];
    const float* b_in     = (const float*)d_in[2];
    const float* leak_tau = (const float*)d_in[3];
    const float* thr      = (const float*)d_in[4];
    const float* W_out    = (const float*)d_in[5];
    const float* b_out    = (const float*)d_in[6];
    float* out = (float*)d_out;

    float* pI; cudaGetSymbolAddress((void**)&pI, g_I);
    __nv_bfloat16 *xa, *xb, *xc, *c1, *c2v, *Wi1, *Wi2, *Wi3, *Wo1, *Wo2;
    cudaGetSymbolAddress((void**)&xa,  g_xa);
    cudaGetSymbolAddress((void**)&xb,  g_xb);
    cudaGetSymbolAddress((void**)&xc,  g_xc);
    cudaGetSymbolAddress((void**)&c1,  g_c1);
    cudaGetSymbolAddress((void**)&c2v, g_c2v);
    cudaGetSymbolAddress((void**)&Wi1, g_Wi1);
    cudaGetSymbolAddress((void**)&Wi2, g_Wi2);
    cudaGetSymbolAddress((void**)&Wi3, g_Wi3);
    cudaGetSymbolAddress((void**)&Wo1, g_Wo1);
    cudaGetSymbolAddress((void**)&Wo2, g_Wo2);

    cudaFuncSetAttribute(gemm_mma<6, 96, false>,
                         cudaFuncAttributeMaxDynamicSharedMemorySize, GEMM_SMEM);
    cudaFuncSetAttribute(gemm_mma<3, 80, true>,
                         cudaFuncAttributeMaxDynamicSharedMemorySize, GEMM_SMEM);

    // Splits
    split3_x<<<2048, 256>>>(x, xa, xb, xc, (size_t)Msz * INsz);
    transpose_split<<<dim3(Hsz / 32, INsz / 32), dim3(32, 8)>>>(
        W_in, INsz, Hsz, Wi1, Wi2, Wi3);
    transpose_split<<<dim3(Hsz / 32, (2 * Hsz) / 32), dim3(32, 8)>>>(
        W_out, 2 * Hsz, Hsz, Wo1, Wo2, nullptr);

    // GEMM1: I = x @ W_in + b_in — 6-term split, small terms first, (1,1) last
    {
        GemmSpec g = {};
        const __nv_bfloat16* As[6] = { xb,  xa,  xb,  xc,  xa,  xa  };
        const __nv_bfloat16* Bs[6] = { Wi1, Wi2, Wi2, Wi1, Wi3, Wi1 };
        for (int p = 0; p < 6; ++p) {
            g.A[p] = As[p]; g.B[p] = Bs[p];
            g.lda[p] = INsz; g.ldb[p] = INsz;
            g.cum[p] = p * 16;
        }
        g.cum[6] = 96;
        gemm_mma<6, 96, false><<<dim3(Hsz / 128, Msz / 128), 256, GEMM_SMEM>>>(
            g, b_in, pI);
    }

    // Chunked parallel scan -> c1, c2v
    {
        dim3 gc(Hsz / 256, Bsz, NC);
        dim3 gs(Hsz / 256, Bsz, 1);
        scan_s1<<<gc, 256>>>(leak_tau);
        scan_s2<<<gs, 256>>>(leak_tau);
        scan_s3<<<gc, 256>>>(leak_tau, thr);
        scan_s4<<<gs, 256>>>();
        scan_s5<<<gc, 256>>>();
    }

    // GEMM2: out = tanh(comb @ W_out + b_out) — (1,2), (2,1), then (1,1) last
    {
        GemmSpec g = {};
        g.A[0] = c1;  g.B[0] = Wo2; g.lda[0] = 2048; g.ldb[0] = 2048;
        g.A[1] = c2v; g.B[1] = Wo1; g.lda[1] = 1024; g.ldb[1] = 2048;
        g.A[2] = c1;  g.B[2] = Wo1; g.lda[2] = 2048; g.ldb[2] = 2048;
        g.cum[0] = 0; g.cum[1] = 32; g.cum[2] = 48; g.cum[3] = 80;
        for (int p = 3; p < 6; ++p) { g.A[p] = c1; g.B[p] = Wo1; g.lda[p] = 2048; g.ldb[p] = 2048; }
        g.cum[4] = g.cum[5] = g.cum[6] = 80;
        gemm_mma<3, 80, true><<<dim3(NG / 128, Msz / 128), 256, GEMM_SMEM>>>(
            g, b_out, out);
    }
}

// round 9
// speedup vs baseline: 3.3429x; 1.2778x over previous
#include <cuda_runtime.h>
#include <cuda_fp16.h>
#include <stdint.h>
#include <math.h>

// ---------------------------------------------------------------------------
// Problem dims
// ---------------------------------------------------------------------------
namespace {
constexpr int Bsz  = 16;
constexpr int Ssz  = 2048;
constexpr int Hsz  = 1024;
constexpr int INsz = 1024;
constexpr int Msz  = Bsz * Ssz;       // 32768
constexpr int NG   = 1024;
constexpr int STAGE_BYTES = 32768;    // 16KB A + 16KB B per stage
constexpr int GEMM_SMEM = 3 * STAGE_BYTES;  // 96 KiB, 3-stage ring
constexpr int NC   = 32;              // scan chunks
constexpr int CL   = Ssz / NC;        // 64 timesteps per chunk
}

// ---------------------------------------------------------------------------
// Scratch (__device__ globals; no allocation allowed)
// ---------------------------------------------------------------------------
__device__ float g_I[(size_t)Msz * Hsz];                   // 128 MiB
__device__ __half g_xa[(size_t)Msz * INsz];                // x 2-way fp16 split
__device__ __half g_xb[(size_t)Msz * INsz];
__device__ __half g_c1[(size_t)Msz * 2 * Hsz];             // [M][2048]: v | s
__device__ __half g_c2v[(size_t)Msz * Hsz];                // [M][1024]: v residual
__device__ __half g_Wi1[(size_t)Hsz * INsz];               // W_in^T fp16 splits [N][K]
__device__ __half g_Wi2[(size_t)Hsz * INsz];
__device__ __half g_Wo1[(size_t)Hsz * 2 * Hsz];            // W_out^T fp16 splits [N][2048]
__device__ __half g_Wo2[(size_t)Hsz * 2 * Hsz];
// scan pipeline scratch: [c][b][h]
__device__ float g_vend [(size_t)NC * Bsz * Hsz];
__device__ float g_vinit[(size_t)NC * Bsz * Hsz];
__device__ int   g_fc   [(size_t)NC * Bsz * Hsz];
__device__ float g_ls   [(size_t)NC * Bsz * Hsz];
__device__ float g_sinit[(size_t)NC * Bsz * Hsz];

// ---------------------------------------------------------------------------
// PTX helpers (base sm_80+ features only)
// ---------------------------------------------------------------------------
#define SWZ128(o) ((o) ^ (((o) >> 3) & 0x70))

__device__ __forceinline__ uint32_t smem_u32(const void* p) {
    uint32_t a;
    asm("{ .reg .u64 t; cvta.to.shared.u64 t, %1; cvt.u32.u64 %0, t; }"
        : "=r"(a) : "l"(p));
    return a;
}
#define CP_ASYNC16(s, g) \
    asm volatile("cp.async.cg.shared.global [%0], [%1], 16;" :: "r"(s), "l"(g))
#define CP_COMMIT()  asm volatile("cp.async.commit_group;" ::: "memory")
#define CP_WAIT0()   asm volatile("cp.async.wait_group 0;" ::: "memory")
#define CP_WAIT1()   asm volatile("cp.async.wait_group 1;" ::: "memory")

__device__ __forceinline__ void ldsm_x4(uint32_t r[4], uint32_t addr) {
    asm volatile("ldmatrix.sync.aligned.m8n8.x4.shared.b16 {%0,%1,%2,%3}, [%4];"
        : "=r"(r[0]), "=r"(r[1]), "=r"(r[2]), "=r"(r[3]) : "r"(addr));
}
__device__ __forceinline__ void mma_fp16(float c[4], const uint32_t a[4],
                                         const uint32_t b[2]) {
    asm volatile(
        "mma.sync.aligned.m16n8k16.row.col.f32.f16.f16.f32 "
        "{%0,%1,%2,%3}, {%4,%5,%6,%7}, {%8,%9}, {%0,%1,%2,%3};"
        : "+f"(c[0]), "+f"(c[1]), "+f"(c[2]), "+f"(c[3])
        : "r"(a[0]), "r"(a[1]), "r"(a[2]), "r"(a[3]), "r"(b[0]), "r"(b[1]));
}

// ---------------------------------------------------------------------------
// Split kernels (fp16 2-way)
// ---------------------------------------------------------------------------
__global__ void split2_x(const float* __restrict__ x, __half* __restrict__ o1,
                         __half* __restrict__ o2, size_t n)
{
    size_t i = (size_t)blockIdx.x * blockDim.x + threadIdx.x;
    size_t stride = (size_t)gridDim.x * blockDim.x;
    for (; i < n; i += stride) {
        float w = x[i];
        __half a = __float2half_rn(w);
        float r = w - __half2float(a);
        o1[i] = a; o2[i] = __float2half_rn(r);
    }
}

// W[K][N] fp32 -> o[N][K] fp16 2-way split
__global__ void transpose_split2(const float* __restrict__ W, int K, int N,
                                 __half* __restrict__ o1,
                                 __half* __restrict__ o2)
{
    __shared__ float t[32][33];
    int n0 = blockIdx.x * 32, k0 = blockIdx.y * 32;
    int tx = threadIdx.x, ty = threadIdx.y;   // (32, 8)
#pragma unroll
    for (int i = 0; i < 4; ++i)
        t[ty + i * 8][tx] = W[(size_t)(k0 + ty + i * 8) * N + n0 + tx];
    __syncthreads();
#pragma unroll
    for (int i = 0; i < 4; ++i) {
        int nn = n0 + ty + i * 8, k = k0 + tx;
        float w = t[tx][ty + i * 8];
        __half a = __float2half_rn(w);
        float r = w - __half2float(a);
        o1[(size_t)nn * K + k] = a;
        o2[(size_t)nn * K + k] = __float2half_rn(r);
    }
}

// ---------------------------------------------------------------------------
// Chunked parallel hysteresis scan (structure proven in R8).
// ---------------------------------------------------------------------------
__device__ __forceinline__ float sig_alpha(const float* lt, int h) {
    return 1.0f / (1.0f + expf(lt[h]));
}

__global__ void scan_s1(const float* __restrict__ leak_tau)
{
    const int h = blockIdx.x * blockDim.x + threadIdx.x;
    const int b = blockIdx.y, c = blockIdx.z;
    const float alpha = sig_alpha(leak_tau, h);
    const float* Ip = g_I + ((size_t)b * Ssz + c * CL) * Hsz + h;
    float v = 0.0f;
#pragma unroll 4
    for (int t = 0; t < CL; ++t)
        v = fmaf(alpha, v, Ip[(size_t)t * Hsz]);
    g_vend[((size_t)c * Bsz + b) * Hsz + h] = v;
}

__global__ void scan_s2(const float* __restrict__ leak_tau)
{
    const int h = blockIdx.x * blockDim.x + threadIdx.x;
    const int b = blockIdx.y;
    const float alpha = sig_alpha(leak_tau, h);
    const float aL = powf(alpha, (float)CL);
    float v = 0.0f;
    for (int c = 0; c < NC; ++c) {
        size_t o = ((size_t)c * Bsz + b) * Hsz + h;
        g_vinit[o] = v;
        v = fmaf(aL, v, g_vend[o]);
    }
}

__global__ void scan_s3(const float* __restrict__ leak_tau,
                        const float* __restrict__ thr_arr)
{
    const int h = blockIdx.x * blockDim.x + threadIdx.x;
    const int b = blockIdx.y, c = blockIdx.z;
    const float alpha = sig_alpha(leak_tau, h);
    const float th = thr_arr[h];
    const size_t co = ((size_t)c * Bsz + b) * Hsz + h;
    float v = g_vinit[co];

    const int t0 = c * CL;
    const float* Ip = g_I + ((size_t)b * Ssz + t0) * Hsz + h;
    __half* c1 = g_c1 + ((size_t)b * Ssz + t0) * 2 * Hsz + h;
    __half* c2 = g_c2v + ((size_t)b * Ssz + t0) * Hsz + h;

    int fc = CL;
    float s = 0.0f;
#pragma unroll 4
    for (int t = 0; t < CL; ++t) {
        v = fmaf(alpha, v, Ip[(size_t)t * Hsz]);
        bool up = v > th, dn = v < -th;
        if (up | dn) {
            if (fc == CL) fc = t;
            s = up ? 1.0f : -1.0f;
        }
        __half v1 = __float2half_rn(v);
        c1[(size_t)t * 2 * Hsz] = v1;
        c2[(size_t)t * Hsz]     = __float2half_rn(v - __half2float(v1));
        if (fc != CL)
            c1[(size_t)t * 2 * Hsz + Hsz] = __float2half_rn(s);
    }
    g_fc[co] = fc;
    g_ls[co] = s;
}

__global__ void scan_s4()
{
    const int h = blockIdx.x * blockDim.x + threadIdx.x;
    const int b = blockIdx.y;
    float s = -1.0f;
    for (int c = 0; c < NC; ++c) {
        size_t o = ((size_t)c * Bsz + b) * Hsz + h;
        g_sinit[o] = s;
        if (g_fc[o] < CL) s = g_ls[o];
    }
}

__global__ void scan_s5()
{
    const int h = blockIdx.x * blockDim.x + threadIdx.x;
    const int b = blockIdx.y, c = blockIdx.z;
    const size_t co = ((size_t)c * Bsz + b) * Hsz + h;
    const int fc = g_fc[co];
    if (fc == 0) return;
    const __half sv = __float2half_rn(g_sinit[co]);
    __half* c1s = g_c1 + ((size_t)b * Ssz + c * CL) * 2 * Hsz + Hsz + h;
    for (int t = 0; t < fc; ++t)
        c1s[(size_t)t * 2 * Hsz] = sv;
}

// ---------------------------------------------------------------------------
// Multi-phase fp16 split-GEMM on mma.sync.
// Pipeline (proven R6): wait -> barrier -> issue(it+2) -> compute(it).
// B fragments loaded pairwise with ldmatrix.x4 (two n-tiles / instruction).
// ---------------------------------------------------------------------------
struct GemmSpec {
    const __half* A[4];
    const __half* B[4];
    int lda[4];
    int ldb[4];
    int cum[5];
};

template<int NPH, int T, bool DO_TANH>
__global__ __launch_bounds__(256, 2)
void gemm_mma(const __grid_constant__ GemmSpec spec,
              const float* __restrict__ bias, float* __restrict__ C)
{
    extern __shared__ __align__(1024) char smem[];
    const uint32_t sb = smem_u32(smem);
    const int tid = threadIdx.x, lane = tid & 31, wid = tid >> 5;
    const int wm = wid >> 2, wn = wid & 3;
    const int m0 = blockIdx.y * 128, n0 = blockIdx.x * 128;

    float acc[4][4][4];
#pragma unroll
    for (int i = 0; i < 4; ++i)
#pragma unroll
        for (int j = 0; j < 4; ++j)
#pragma unroll
            for (int k = 0; k < 4; ++k) acc[i][j][k] = 0.0f;

    auto issue_loads = [&](int it) {
        int ph = 0;
#pragma unroll
        for (int p = 0; p < NPH - 1; ++p) if (it >= spec.cum[p + 1]) ph = p + 1;
        const int kt = (it - spec.cum[ph]) * 64;
        const int lda = spec.lda[ph], ldb = spec.ldb[ph];
        const char* Apc = (const char*)spec.A[ph];
        const char* Bpc = (const char*)spec.B[ph];
        const uint32_t sA = sb + (it % 3) * STAGE_BYTES;
        const uint32_t sB = sA + 16384;
#pragma unroll
        for (int i = 0; i < 4; ++i) {
            int id = tid + 256 * i;
            int r = id >> 3, cb = (id & 7) * 16;
            CP_ASYNC16(sA + SWZ128(r * 128 + cb),
                       Apc + ((size_t)(m0 + r) * lda + kt) * 2 + cb);
            CP_ASYNC16(sB + SWZ128(r * 128 + cb),
                       Bpc + ((size_t)(n0 + r) * ldb + kt) * 2 + cb);
        }
    };

    issue_loads(0); CP_COMMIT();
    issue_loads(1); CP_COMMIT();

#pragma unroll 1
    for (int it = 0; it < T; ++it) {
        if (it + 1 < T) { CP_WAIT1(); } else { CP_WAIT0(); }
        __syncthreads();
        if (it + 2 < T) { issue_loads(it + 2); CP_COMMIT(); }

        const uint32_t sA = sb + (it % 3) * STAGE_BYTES;
        const uint32_t sB = sA + 16384;
#pragma unroll
        for (int kk = 0; kk < 4; ++kk) {
            uint32_t aF[4][4], bF[4][2];
#pragma unroll
            for (int mt = 0; mt < 4; ++mt) {
                int row = wm * 64 + mt * 16 + (lane & 15);
                int colb = kk * 32 + (lane >> 4) * 16;
                ldsm_x4(aF[mt], sA + SWZ128(row * 128 + colb));
            }
            // B: two n-tiles per ldmatrix.x4
            // matrix id m = lane>>3: row group 2*np + (m>>1), k-chunk (m&1)*16B
#pragma unroll
            for (int np = 0; np < 2; ++np) {
                int mat = lane >> 3;
                int row = wn * 32 + (2 * np + (mat >> 1)) * 8 + (lane & 7);
                int colb = kk * 32 + (mat & 1) * 16;
                uint32_t r4[4];
                ldsm_x4(r4, sB + SWZ128(row * 128 + colb));
                bF[2 * np][0] = r4[0]; bF[2 * np][1] = r4[1];
                bF[2 * np + 1][0] = r4[2]; bF[2 * np + 1][1] = r4[3];
            }
#pragma unroll
            for (int mt = 0; mt < 4; ++mt)
#pragma unroll
                for (int nt = 0; nt < 4; ++nt)
                    mma_fp16(acc[mt][nt], aF[mt], bF[nt]);
        }
    }

    const int gid = lane >> 2, tig = lane & 3;
#pragma unroll
    for (int mt = 0; mt < 4; ++mt) {
#pragma unroll
        for (int nt = 0; nt < 4; ++nt) {
            int col = n0 + wn * 32 + nt * 8 + 2 * tig;
            float2 bv = *reinterpret_cast<const float2*>(&bias[col]);
            int r0 = m0 + wm * 64 + mt * 16 + gid;
            float2 v0, v1;
            v0.x = acc[mt][nt][0] + bv.x; v0.y = acc[mt][nt][1] + bv.y;
            v1.x = acc[mt][nt][2] + bv.x; v1.y = acc[mt][nt][3] + bv.y;
            if (DO_TANH) {
                v0.x = tanhf(v0.x); v0.y = tanhf(v0.y);
                v1.x = tanhf(v1.x); v1.y = tanhf(v1.y);
            }
            *reinterpret_cast<float2*>(&C[(size_t)r0 * NG + col]) = v0;
            *reinterpret_cast<float2*>(&C[(size_t)(r0 + 8) * NG + col]) = v1;
        }
    }
}

// ---------------------------------------------------------------------------
extern "C" void kernel_launch(void* const* d_in, const int* in_sizes, int n_in,
                              void* d_out, int out_size)
{
    const float* x        = (const float*)d_in[0];
    const float* W_in     = (const float*)d_in[1];
    const float* b_in     = (const float*)d_in[2];
    const float* leak_tau = (const float*)d_in[3];
    const float* thr      = (const float*)d_in[4];
    const float* W_out    = (const float*)d_in[5];
    const float* b_out    = (const float*)d_in[6];
    float* out = (float*)d_out;

    float* pI; cudaGetSymbolAddress((void**)&pI, g_I);
    __half *xa, *xb, *c1, *c2v, *Wi1, *Wi2, *Wo1, *Wo2;
    cudaGetSymbolAddress((void**)&xa,  g_xa);
    cudaGetSymbolAddress((void**)&xb,  g_xb);
    cudaGetSymbolAddress((void**)&c1,  g_c1);
    cudaGetSymbolAddress((void**)&c2v, g_c2v);
    cudaGetSymbolAddress((void**)&Wi1, g_Wi1);
    cudaGetSymbolAddress((void**)&Wi2, g_Wi2);
    cudaGetSymbolAddress((void**)&Wo1, g_Wo1);
    cudaGetSymbolAddress((void**)&Wo2, g_Wo2);

    cudaFuncSetAttribute(gemm_mma<4, 64, false>,
                         cudaFuncAttributeMaxDynamicSharedMemorySize, GEMM_SMEM);
    cudaFuncSetAttribute(gemm_mma<3, 80, true>,
                         cudaFuncAttributeMaxDynamicSharedMemorySize, GEMM_SMEM);

    // Splits (fp16 2-way)
    split2_x<<<2048, 256>>>(x, xa, xb, (size_t)Msz * INsz);
    transpose_split2<<<dim3(Hsz / 32, INsz / 32), dim3(32, 8)>>>(
        W_in, INsz, Hsz, Wi1, Wi2);
    transpose_split2<<<dim3(Hsz / 32, (2 * Hsz) / 32), dim3(32, 8)>>>(
        W_out, 2 * Hsz, Hsz, Wo1, Wo2);

    // GEMM1: I = x @ W_in + b_in — 4-term fp16 split, small terms first:
    //   (2,2) xb*Wi2, (2,1) xb*Wi1, (1,2) xa*Wi2, (1,1) xa*Wi1  (16 iters each)
    {
        GemmSpec g = {};
        const __half* As[4] = { xb,  xb,  xa,  xa  };
        const __half* Bs[4] = { Wi2, Wi1, Wi2, Wi1 };
        for (int p = 0; p < 4; ++p) {
            g.A[p] = As[p]; g.B[p] = Bs[p];
            g.lda[p] = INsz; g.ldb[p] = INsz;
            g.cum[p] = p * 16;
        }
        g.cum[4] = 64;
        gemm_mma<4, 64, false><<<dim3(Hsz / 128, Msz / 128), 256, GEMM_SMEM>>>(
            g, b_in, pI);
    }

    // Chunked parallel scan -> c1, c2v
    {
        dim3 gc(Hsz / 256, Bsz, NC);
        dim3 gs(Hsz / 256, Bsz, 1);
        scan_s1<<<gc, 256>>>(leak_tau);
        scan_s2<<<gs, 256>>>(leak_tau);
        scan_s3<<<gc, 256>>>(leak_tau, thr);
        scan_s4<<<gs, 256>>>();
        scan_s5<<<gc, 256>>>();
    }

    // GEMM2: out = tanh(comb @ W_out + b_out) — (1,2), (2,1), (1,1) last
    {
        GemmSpec g = {};
        g.A[0] = c1;  g.B[0] = Wo2; g.lda[0] = 2048; g.ldb[0] = 2048;
        g.A[1] = c2v; g.B[1] = Wo1; g.lda[1] = 1024; g.ldb[1] = 2048;
        g.A[2] = c1;  g.B[2] = Wo1; g.lda[2] = 2048; g.ldb[2] = 2048;
        g.A[3] = c1;  g.B[3] = Wo1; g.lda[3] = 2048; g.ldb[3] = 2048; // unused
        g.cum[0] = 0; g.cum[1] = 32; g.cum[2] = 48; g.cum[3] = 80; g.cum[4] = 80;
        gemm_mma<3, 80, true><<<dim3(NG / 128, Msz / 128), 256, GEMM_SMEM>>>(
            g, b_out, out);
    }
}

// round 10
// speedup vs baseline: 3.6476x; 1.0911x over previous
#include <cuda_runtime.h>
#include <cuda_fp16.h>
#include <stdint.h>
#include <math.h>

// ---------------------------------------------------------------------------
// Problem dims
// ---------------------------------------------------------------------------
namespace {
constexpr int Bsz  = 16;
constexpr int Ssz  = 2048;
constexpr int Hsz  = 1024;
constexpr int INsz = 1024;
constexpr int Msz  = Bsz * Ssz;       // 32768
constexpr int NG   = 1024;
constexpr int STAGE_BYTES = 32768;    // 16KB A + 16KB B per stage
constexpr int GEMM_SMEM = 3 * STAGE_BYTES;  // 96 KiB, 3-stage ring
constexpr int NC   = 32;              // scan chunks
constexpr int CL   = Ssz / NC;        // 64 timesteps per chunk
}

// ---------------------------------------------------------------------------
// Scratch (__device__ globals; no allocation allowed)
// ---------------------------------------------------------------------------
__device__ float g_I[(size_t)Msz * Hsz];                   // 128 MiB
__device__ __half g_xa[(size_t)Msz * INsz];                // x 2-way fp16 split
__device__ __half g_xb[(size_t)Msz * INsz];
__device__ __half g_c1[(size_t)Msz * 2 * Hsz];             // [M][2048]: v | s
__device__ __half g_c2v[(size_t)Msz * Hsz];                // [M][1024]: v residual
__device__ __half g_Wi1[(size_t)Hsz * INsz];               // W_in^T fp16 splits [N][K]
__device__ __half g_Wi2[(size_t)Hsz * INsz];
__device__ __half g_Wo1[(size_t)Hsz * 2 * Hsz];            // W_out^T fp16 splits [N][2048]
__device__ __half g_Wo2[(size_t)Hsz * 2 * Hsz];
// scan pipeline scratch: [c][b][h]
__device__ float g_vend [(size_t)NC * Bsz * Hsz];
__device__ float g_vinit[(size_t)NC * Bsz * Hsz];
__device__ int   g_fc   [(size_t)NC * Bsz * Hsz];
__device__ float g_ls   [(size_t)NC * Bsz * Hsz];
__device__ float g_sinit[(size_t)NC * Bsz * Hsz];

// ---------------------------------------------------------------------------
// PTX helpers (base sm_80+ features only)
// ---------------------------------------------------------------------------
#define SWZ128(o) ((o) ^ (((o) >> 3) & 0x70))

__device__ __forceinline__ uint32_t smem_u32(const void* p) {
    uint32_t a;
    asm("{ .reg .u64 t; cvta.to.shared.u64 t, %1; cvt.u32.u64 %0, t; }"
        : "=r"(a) : "l"(p));
    return a;
}
#define CP_ASYNC16(s, g) \
    asm volatile("cp.async.cg.shared.global [%0], [%1], 16;" :: "r"(s), "l"(g))
#define CP_COMMIT()  asm volatile("cp.async.commit_group;" ::: "memory")
#define CP_WAIT0()   asm volatile("cp.async.wait_group 0;" ::: "memory")
#define CP_WAIT1()   asm volatile("cp.async.wait_group 1;" ::: "memory")

__device__ __forceinline__ void ldsm_x4(uint32_t r[4], uint32_t addr) {
    asm volatile("ldmatrix.sync.aligned.m8n8.x4.shared.b16 {%0,%1,%2,%3}, [%4];"
        : "=r"(r[0]), "=r"(r[1]), "=r"(r[2]), "=r"(r[3]) : "r"(addr));
}
__device__ __forceinline__ void mma_fp16(float c[4], const uint32_t a[4],
                                         const uint32_t b[2]) {
    asm volatile(
        "mma.sync.aligned.m16n8k16.row.col.f32.f16.f16.f32 "
        "{%0,%1,%2,%3}, {%4,%5,%6,%7}, {%8,%9}, {%0,%1,%2,%3};"
        : "+f"(c[0]), "+f"(c[1]), "+f"(c[2]), "+f"(c[3])
        : "r"(a[0]), "r"(a[1]), "r"(a[2]), "r"(a[3]), "r"(b[0]), "r"(b[1]));
}

// ---------------------------------------------------------------------------
// Split kernels (fp16 2-way)
// ---------------------------------------------------------------------------
__global__ void split2_x(const float* __restrict__ x, __half* __restrict__ o1,
                         __half* __restrict__ o2, size_t n)
{
    size_t i = (size_t)blockIdx.x * blockDim.x + threadIdx.x;
    size_t stride = (size_t)gridDim.x * blockDim.x;
    for (; i < n; i += stride) {
        float w = x[i];
        __half a = __float2half_rn(w);
        float r = w - __half2float(a);
        o1[i] = a; o2[i] = __float2half_rn(r);
    }
}

// W[K][N] fp32 -> o[N][K] fp16 2-way split
__global__ void transpose_split2(const float* __restrict__ W, int K, int N,
                                 __half* __restrict__ o1,
                                 __half* __restrict__ o2)
{
    __shared__ float t[32][33];
    int n0 = blockIdx.x * 32, k0 = blockIdx.y * 32;
    int tx = threadIdx.x, ty = threadIdx.y;   // (32, 8)
#pragma unroll
    for (int i = 0; i < 4; ++i)
        t[ty + i * 8][tx] = W[(size_t)(k0 + ty + i * 8) * N + n0 + tx];
    __syncthreads();
#pragma unroll
    for (int i = 0; i < 4; ++i) {
        int nn = n0 + ty + i * 8, k = k0 + tx;
        float w = t[tx][ty + i * 8];
        __half a = __float2half_rn(w);
        float r = w - __half2float(a);
        o1[(size_t)nn * K + k] = a;
        o2[(size_t)nn * K + k] = __float2half_rn(r);
    }
}

// ---------------------------------------------------------------------------
// Chunked parallel hysteresis scan (proven in R8).
// ---------------------------------------------------------------------------
__device__ __forceinline__ float sig_alpha(const float* lt, int h) {
    return 1.0f / (1.0f + expf(lt[h]));
}

__global__ void scan_s1(const float* __restrict__ leak_tau)
{
    const int h = blockIdx.x * blockDim.x + threadIdx.x;
    const int b = blockIdx.y, c = blockIdx.z;
    const float alpha = sig_alpha(leak_tau, h);
    const float* Ip = g_I + ((size_t)b * Ssz + c * CL) * Hsz + h;
    float v = 0.0f;
#pragma unroll 4
    for (int t = 0; t < CL; ++t)
        v = fmaf(alpha, v, Ip[(size_t)t * Hsz]);
    g_vend[((size_t)c * Bsz + b) * Hsz + h] = v;
}

__global__ void scan_s2(const float* __restrict__ leak_tau)
{
    const int h = blockIdx.x * blockDim.x + threadIdx.x;
    const int b = blockIdx.y;
    const float alpha = sig_alpha(leak_tau, h);
    const float aL = powf(alpha, (float)CL);
    float v = 0.0f;
    for (int c = 0; c < NC; ++c) {
        size_t o = ((size_t)c * Bsz + b) * Hsz + h;
        g_vinit[o] = v;
        v = fmaf(aL, v, g_vend[o]);
    }
}

__global__ void scan_s3(const float* __restrict__ leak_tau,
                        const float* __restrict__ thr_arr)
{
    const int h = blockIdx.x * blockDim.x + threadIdx.x;
    const int b = blockIdx.y, c = blockIdx.z;
    const float alpha = sig_alpha(leak_tau, h);
    const float th = thr_arr[h];
    const size_t co = ((size_t)c * Bsz + b) * Hsz + h;
    float v = g_vinit[co];

    const int t0 = c * CL;
    const float* Ip = g_I + ((size_t)b * Ssz + t0) * Hsz + h;
    __half* c1 = g_c1 + ((size_t)b * Ssz + t0) * 2 * Hsz + h;
    __half* c2 = g_c2v + ((size_t)b * Ssz + t0) * Hsz + h;

    int fc = CL;
    float s = 0.0f;
#pragma unroll 4
    for (int t = 0; t < CL; ++t) {
        v = fmaf(alpha, v, Ip[(size_t)t * Hsz]);
        bool up = v > th, dn = v < -th;
        if (up | dn) {
            if (fc == CL) fc = t;
            s = up ? 1.0f : -1.0f;
        }
        __half v1 = __float2half_rn(v);
        c1[(size_t)t * 2 * Hsz] = v1;
        c2[(size_t)t * Hsz]     = __float2half_rn(v - __half2float(v1));
        if (fc != CL)
            c1[(size_t)t * 2 * Hsz + Hsz] = __float2half_rn(s);
    }
    g_fc[co] = fc;
    g_ls[co] = s;
}

__global__ void scan_s4()
{
    const int h = blockIdx.x * blockDim.x + threadIdx.x;
    const int b = blockIdx.y;
    float s = -1.0f;
    for (int c = 0; c < NC; ++c) {
        size_t o = ((size_t)c * Bsz + b) * Hsz + h;
        g_sinit[o] = s;
        if (g_fc[o] < CL) s = g_ls[o];
    }
}

__global__ void scan_s5()
{
    const int h = blockIdx.x * blockDim.x + threadIdx.x;
    const int b = blockIdx.y, c = blockIdx.z;
    const size_t co = ((size_t)c * Bsz + b) * Hsz + h;
    const int fc = g_fc[co];
    if (fc == 0) return;
    const __half sv = __float2half_rn(g_sinit[co]);
    __half* c1s = g_c1 + ((size_t)b * Ssz + c * CL) * 2 * Hsz + Hsz + h;
    for (int t = 0; t < fc; ++t)
        c1s[(size_t)t * 2 * Hsz] = sv;
}

// ---------------------------------------------------------------------------
// Multi-phase fp16 split-GEMM on mma.sync.
// Pipeline (proven R6): wait -> barrier -> issue(it+2) -> compute(it).
// B pairs loaded via ldmatrix.x4. LDSM swizzle-XOR hoisted (row-only mask).
// ---------------------------------------------------------------------------
struct GemmSpec {
    const __half* A[3];
    const __half* B[3];
    int lda[3];
    int ldb[3];
    int cum[4];
};

template<int NPH, int T, bool DO_TANH>
__global__ __launch_bounds__(256, 2)
void gemm_mma(const __grid_constant__ GemmSpec spec,
              const float* __restrict__ bias, float* __restrict__ C)
{
    extern __shared__ __align__(1024) char smem[];
    const uint32_t sb = smem_u32(smem);
    const int tid = threadIdx.x, lane = tid & 31, wid = tid >> 5;
    const int wm = wid >> 2, wn = wid & 3;
    const int m0 = blockIdx.y * 128, n0 = blockIdx.x * 128;

    float acc[4][4][4];
#pragma unroll
    for (int i = 0; i < 4; ++i)
#pragma unroll
        for (int j = 0; j < 4; ++j)
#pragma unroll
            for (int k = 0; k < 4; ++k) acc[i][j][k] = 0.0f;

    // Hoisted LDSM addressing: offset = row*128 + (col ^ ((row&7)<<4)).
    // A-side: 4 row bases + their XOR masks; col = kk*32 + (lane>>4)*16.
    uint32_t aBase[4], aXm;
    {
        int r0 = wm * 64 + (lane & 15);
#pragma unroll
        for (int mt = 0; mt < 4; ++mt) aBase[mt] = (uint32_t)((r0 + mt * 16) * 128);
        aXm = (uint32_t)(((r0 & 7) << 4));
    }
    const uint32_t aCol0 = (uint32_t)((lane >> 4) * 16);
    // B-side: pairwise x4; mat = lane>>3.
    uint32_t bBase[2], bXm;
    {
        int mat = lane >> 3;
        int rb = wn * 32 + (mat >> 1) * 8 + (lane & 7);
#pragma unroll
        for (int np = 0; np < 2; ++np) bBase[np] = (uint32_t)((rb + np * 16) * 128);
        bXm = (uint32_t)(((rb & 7) << 4));
        bBase[0] += 0; // col added per kk
    }
    const uint32_t bCol0 = (uint32_t)(((lane >> 3) & 1) * 16);

    auto issue_loads = [&](int it) {
        int ph = 0;
#pragma unroll
        for (int p = 0; p < NPH - 1; ++p) if (it >= spec.cum[p + 1]) ph = p + 1;
        const int kt = (it - spec.cum[ph]) * 64;
        const int lda = spec.lda[ph], ldb = spec.ldb[ph];
        const char* Apc = (const char*)spec.A[ph];
        const char* Bpc = (const char*)spec.B[ph];
        const uint32_t sA = sb + (it % 3) * STAGE_BYTES;
        const uint32_t sB = sA + 16384;
#pragma unroll
        for (int i = 0; i < 4; ++i) {
            int id = tid + 256 * i;
            int r = id >> 3, cb = (id & 7) * 16;
            CP_ASYNC16(sA + SWZ128(r * 128 + cb),
                       Apc + ((size_t)(m0 + r) * lda + kt) * 2 + cb);
            CP_ASYNC16(sB + SWZ128(r * 128 + cb),
                       Bpc + ((size_t)(n0 + r) * ldb + kt) * 2 + cb);
        }
    };

    issue_loads(0); CP_COMMIT();
    issue_loads(1); CP_COMMIT();

#pragma unroll 1
    for (int it = 0; it < T; ++it) {
        if (it + 1 < T) { CP_WAIT1(); } else { CP_WAIT0(); }
        __syncthreads();
        if (it + 2 < T) { issue_loads(it + 2); CP_COMMIT(); }

        const uint32_t sA = sb + (it % 3) * STAGE_BYTES;
        const uint32_t sB = sA + 16384;
#pragma unroll
        for (int kk = 0; kk < 4; ++kk) {
            uint32_t aF[4][4], bF[4][2];
            const uint32_t aCol = ((uint32_t)(kk * 32) + aCol0) ^ aXm;
            const uint32_t bCol = ((uint32_t)(kk * 32) + bCol0) ^ bXm;
#pragma unroll
            for (int mt = 0; mt < 4; ++mt)
                ldsm_x4(aF[mt], sA + aBase[mt] + aCol);
#pragma unroll
            for (int np = 0; np < 2; ++np) {
                uint32_t r4[4];
                ldsm_x4(r4, sB + bBase[np] + bCol);
                bF[2 * np][0] = r4[0]; bF[2 * np][1] = r4[1];
                bF[2 * np + 1][0] = r4[2]; bF[2 * np + 1][1] = r4[3];
            }
#pragma unroll
            for (int mt = 0; mt < 4; ++mt)
#pragma unroll
                for (int nt = 0; nt < 4; ++nt)
                    mma_fp16(acc[mt][nt], aF[mt], bF[nt]);
        }
    }

    const int gid = lane >> 2, tig = lane & 3;
#pragma unroll
    for (int mt = 0; mt < 4; ++mt) {
#pragma unroll
        for (int nt = 0; nt < 4; ++nt) {
            int col = n0 + wn * 32 + nt * 8 + 2 * tig;
            float2 bv = *reinterpret_cast<const float2*>(&bias[col]);
            int r0 = m0 + wm * 64 + mt * 16 + gid;
            float2 v0, v1;
            v0.x = acc[mt][nt][0] + bv.x; v0.y = acc[mt][nt][1] + bv.y;
            v1.x = acc[mt][nt][2] + bv.x; v1.y = acc[mt][nt][3] + bv.y;
            if (DO_TANH) {
                v0.x = tanhf(v0.x); v0.y = tanhf(v0.y);
                v1.x = tanhf(v1.x); v1.y = tanhf(v1.y);
            }
            *reinterpret_cast<float2*>(&C[(size_t)r0 * NG + col]) = v0;
            *reinterpret_cast<float2*>(&C[(size_t)(r0 + 8) * NG + col]) = v1;
        }
    }
}

// ---------------------------------------------------------------------------
extern "C" void kernel_launch(void* const* d_in, const int* in_sizes, int n_in,
                              void* d_out, int out_size)
{
    const float* x        = (const float*)d_in[0];
    const float* W_in     = (const float*)d_in[1];
    const float* b_in     = (const float*)d_in[2];
    const float* leak_tau = (const float*)d_in[3];
    const float* thr      = (const float*)d_in[4];
    const float* W_out    = (const float*)d_in[5];
    const float* b_out    = (const float*)d_in[6];
    float* out = (float*)d_out;

    float* pI; cudaGetSymbolAddress((void**)&pI, g_I);
    __half *xa, *xb, *c1, *c2v, *Wi1, *Wi2, *Wo1, *Wo2;
    cudaGetSymbolAddress((void**)&xa,  g_xa);
    cudaGetSymbolAddress((void**)&xb,  g_xb);
    cudaGetSymbolAddress((void**)&c1,  g_c1);
    cudaGetSymbolAddress((void**)&c2v, g_c2v);
    cudaGetSymbolAddress((void**)&Wi1, g_Wi1);
    cudaGetSymbolAddress((void**)&Wi2, g_Wi2);
    cudaGetSymbolAddress((void**)&Wo1, g_Wo1);
    cudaGetSymbolAddress((void**)&Wo2, g_Wo2);

    cudaFuncSetAttribute(gemm_mma<3, 48, false>,
                         cudaFuncAttributeMaxDynamicSharedMemorySize, GEMM_SMEM);
    cudaFuncSetAttribute(gemm_mma<3, 80, true>,
                         cudaFuncAttributeMaxDynamicSharedMemorySize, GEMM_SMEM);

    // Splits (fp16 2-way)
    split2_x<<<2048, 256>>>(x, xa, xb, (size_t)Msz * INsz);
    transpose_split2<<<dim3(Hsz / 32, INsz / 32), dim3(32, 8)>>>(
        W_in, INsz, Hsz, Wi1, Wi2);
    transpose_split2<<<dim3(Hsz / 32, (2 * Hsz) / 32), dim3(32, 8)>>>(
        W_out, 2 * Hsz, Hsz, Wo1, Wo2);

    // GEMM1: I = x @ W_in + b_in — 3-term fp16 split ((2,2) dropped: ~2e-7
    //        noise, below fp32 accumulation class). Small terms first:
    //   (2,1) xb*Wi1, (1,2) xa*Wi2, (1,1) xa*Wi1  (16 iters each)
    {
        GemmSpec g = {};
        const __half* As[3] = { xb,  xa,  xa  };
        const __half* Bs[3] = { Wi1, Wi2, Wi1 };
        for (int p = 0; p < 3; ++p) {
            g.A[p] = As[p]; g.B[p] = Bs[p];
            g.lda[p] = INsz; g.ldb[p] = INsz;
            g.cum[p] = p * 16;
        }
        g.cum[3] = 48;
        gemm_mma<3, 48, false><<<dim3(Hsz / 128, Msz / 128), 256, GEMM_SMEM>>>(
            g, b_in, pI);
    }

    // Chunked parallel scan -> c1, c2v
    {
        dim3 gc(Hsz / 256, Bsz, NC);
        dim3 gs(Hsz / 256, Bsz, 1);
        scan_s1<<<gc, 256>>>(leak_tau);
        scan_s2<<<gs, 256>>>(leak_tau);
        scan_s3<<<gc, 256>>>(leak_tau, thr);
        scan_s4<<<gs, 256>>>();
        scan_s5<<<gc, 256>>>();
    }

    // GEMM2: out = tanh(comb @ W_out + b_out) — (1,2), (2,1), (1,1) last
    {
        GemmSpec g = {};
        g.A[0] = c1;  g.B[0] = Wo2; g.lda[0] = 2048; g.ldb[0] = 2048;
        g.A[1] = c2v; g.B[1] = Wo1; g.lda[1] = 1024; g.ldb[1] = 2048;
        g.A[2] = c1;  g.B[2] = Wo1; g.lda[2] = 2048; g.ldb[2] = 2048;
        g.cum[0] = 0; g.cum[1] = 32; g.cum[2] = 48; g.cum[3] = 80;
        gemm_mma<3, 80, true><<<dim3(NG / 128, Msz / 128), 256, GEMM_SMEM>>>(
            g, b_out, out);
    }
}

// round 11
// speedup vs baseline: 4.5527x; 1.2482x over previous
#include <cuda_runtime.h>
#include <cuda_fp16.h>
#include <stdint.h>
#include <math.h>

// ---------------------------------------------------------------------------
// Problem dims
// ---------------------------------------------------------------------------
namespace {
constexpr int Bsz  = 16;
constexpr int Ssz  = 2048;
constexpr int Hsz  = 1024;
constexpr int INsz = 1024;
constexpr int Msz  = Bsz * Ssz;       // 32768
constexpr int NG   = 1024;
constexpr int STAGE_BYTES = 32768;    // 16KB A + 16KB B per stage
constexpr int GEMM_SMEM = 3 * STAGE_BYTES;  // 96 KiB, 3-stage ring
constexpr int NC   = 32;              // scan chunks
constexpr int CL   = Ssz / NC;        // 64 timesteps per chunk
}

// ---------------------------------------------------------------------------
// Scratch (__device__ globals; no allocation allowed)
// ---------------------------------------------------------------------------
__device__ float g_I[(size_t)Msz * Hsz];                   // 128 MiB
__device__ __half g_xa[(size_t)Msz * INsz];                // x 2-way fp16 split
__device__ __half g_xb[(size_t)Msz * INsz];
__device__ __half g_c1[(size_t)Msz * 2 * Hsz];             // [M][2048]: v | s
__device__ __half g_c2v[(size_t)Msz * Hsz];                // [M][1024]: v residual
__device__ __half g_Wi1[(size_t)Hsz * INsz];               // W_in^T fp16 splits [N][K]
__device__ __half g_Wi2[(size_t)Hsz * INsz];
__device__ __half g_Wo1[(size_t)Hsz * 2 * Hsz];            // W_out^T fp16 [N][2048]
// scan pipeline scratch: [c][b][h]
__device__ float g_vend [(size_t)NC * Bsz * Hsz];
__device__ float g_vinit[(size_t)NC * Bsz * Hsz];
__device__ int   g_fc   [(size_t)NC * Bsz * Hsz];
__device__ float g_ls   [(size_t)NC * Bsz * Hsz];
__device__ float g_sinit[(size_t)NC * Bsz * Hsz];

// ---------------------------------------------------------------------------
// PTX helpers (base sm_80+ features only)
// ---------------------------------------------------------------------------
#define SWZ128(o) ((o) ^ (((o) >> 3) & 0x70))

__device__ __forceinline__ uint32_t smem_u32(const void* p) {
    uint32_t a;
    asm("{ .reg .u64 t; cvta.to.shared.u64 t, %1; cvt.u32.u64 %0, t; }"
        : "=r"(a) : "l"(p));
    return a;
}
#define CP_ASYNC16(s, g) \
    asm volatile("cp.async.cg.shared.global [%0], [%1], 16;" :: "r"(s), "l"(g))
#define CP_COMMIT()  asm volatile("cp.async.commit_group;" ::: "memory")
#define CP_WAIT0()   asm volatile("cp.async.wait_group 0;" ::: "memory")
#define CP_WAIT1()   asm volatile("cp.async.wait_group 1;" ::: "memory")

__device__ __forceinline__ void ldsm_x4(uint32_t r[4], uint32_t addr) {
    asm volatile("ldmatrix.sync.aligned.m8n8.x4.shared.b16 {%0,%1,%2,%3}, [%4];"
        : "=r"(r[0]), "=r"(r[1]), "=r"(r[2]), "=r"(r[3]) : "r"(addr));
}
__device__ __forceinline__ void mma_fp16(float c[4], const uint32_t a[4],
                                         const uint32_t b[2]) {
    asm volatile(
        "mma.sync.aligned.m16n8k16.row.col.f32.f16.f16.f32 "
        "{%0,%1,%2,%3}, {%4,%5,%6,%7}, {%8,%9}, {%0,%1,%2,%3};"
        : "+f"(c[0]), "+f"(c[1]), "+f"(c[2]), "+f"(c[3])
        : "r"(a[0]), "r"(a[1]), "r"(a[2]), "r"(a[3]), "r"(b[0]), "r"(b[1]));
}

// ---------------------------------------------------------------------------
// Split kernels (fp16 2-way)
// ---------------------------------------------------------------------------
__global__ void split2_x(const float* __restrict__ x, __half* __restrict__ o1,
                         __half* __restrict__ o2, size_t n)
{
    size_t i = (size_t)blockIdx.x * blockDim.x + threadIdx.x;
    size_t stride = (size_t)gridDim.x * blockDim.x;
    for (; i < n; i += stride) {
        float w = x[i];
        __half a = __float2half_rn(w);
        float r = w - __half2float(a);
        o1[i] = a; o2[i] = __float2half_rn(r);
    }
}

// W[K][N] fp32 -> o[N][K] fp16 2-way split (o2 optional)
__global__ void transpose_split2(const float* __restrict__ W, int K, int N,
                                 __half* __restrict__ o1,
                                 __half* __restrict__ o2)
{
    __shared__ float t[32][33];
    int n0 = blockIdx.x * 32, k0 = blockIdx.y * 32;
    int tx = threadIdx.x, ty = threadIdx.y;   // (32, 8)
#pragma unroll
    for (int i = 0; i < 4; ++i)
        t[ty + i * 8][tx] = W[(size_t)(k0 + ty + i * 8) * N + n0 + tx];
    __syncthreads();
#pragma unroll
    for (int i = 0; i < 4; ++i) {
        int nn = n0 + ty + i * 8, k = k0 + tx;
        float w = t[tx][ty + i * 8];
        __half a = __float2half_rn(w);
        o1[(size_t)nn * K + k] = a;
        if (o2) {
            float r = w - __half2float(a);
            o2[(size_t)nn * K + k] = __float2half_rn(r);
        }
    }
}

// ---------------------------------------------------------------------------
// Chunked parallel hysteresis scan (proven in R8).
// ---------------------------------------------------------------------------
__device__ __forceinline__ float sig_alpha(const float* lt, int h) {
    return 1.0f / (1.0f + expf(lt[h]));
}

__global__ void scan_s1(const float* __restrict__ leak_tau)
{
    const int h = blockIdx.x * blockDim.x + threadIdx.x;
    const int b = blockIdx.y, c = blockIdx.z;
    const float alpha = sig_alpha(leak_tau, h);
    const float* Ip = g_I + ((size_t)b * Ssz + c * CL) * Hsz + h;
    float v = 0.0f;
#pragma unroll 4
    for (int t = 0; t < CL; ++t)
        v = fmaf(alpha, v, Ip[(size_t)t * Hsz]);
    g_vend[((size_t)c * Bsz + b) * Hsz + h] = v;
}

__global__ void scan_s2(const float* __restrict__ leak_tau)
{
    const int h = blockIdx.x * blockDim.x + threadIdx.x;
    const int b = blockIdx.y;
    const float alpha = sig_alpha(leak_tau, h);
    const float aL = powf(alpha, (float)CL);
    float v = 0.0f;
    for (int c = 0; c < NC; ++c) {
        size_t o = ((size_t)c * Bsz + b) * Hsz + h;
        g_vinit[o] = v;
        v = fmaf(aL, v, g_vend[o]);
    }
}

__global__ void scan_s3(const float* __restrict__ leak_tau,
                        const float* __restrict__ thr_arr)
{
    const int h = blockIdx.x * blockDim.x + threadIdx.x;
    const int b = blockIdx.y, c = blockIdx.z;
    const float alpha = sig_alpha(leak_tau, h);
    const float th = thr_arr[h];
    const size_t co = ((size_t)c * Bsz + b) * Hsz + h;
    float v = g_vinit[co];

    const int t0 = c * CL;
    const float* Ip = g_I + ((size_t)b * Ssz + t0) * Hsz + h;
    __half* c1 = g_c1 + ((size_t)b * Ssz + t0) * 2 * Hsz + h;
    __half* c2 = g_c2v + ((size_t)b * Ssz + t0) * Hsz + h;

    int fc = CL;
    float s = 0.0f;
#pragma unroll 4
    for (int t = 0; t < CL; ++t) {
        v = fmaf(alpha, v, Ip[(size_t)t * Hsz]);
        bool up = v > th, dn = v < -th;
        if (up | dn) {
            if (fc == CL) fc = t;
            s = up ? 1.0f : -1.0f;
        }
        __half v1 = __float2half_rn(v);
        c1[(size_t)t * 2 * Hsz] = v1;
        c2[(size_t)t * Hsz]     = __float2half_rn(v - __half2float(v1));
        if (fc != CL)
            c1[(size_t)t * 2 * Hsz + Hsz] = __float2half_rn(s);
    }
    g_fc[co] = fc;
    g_ls[co] = s;
}

__global__ void scan_s4()
{
    const int h = blockIdx.x * blockDim.x + threadIdx.x;
    const int b = blockIdx.y;
    float s = -1.0f;
    for (int c = 0; c < NC; ++c) {
        size_t o = ((size_t)c * Bsz + b) * Hsz + h;
        g_sinit[o] = s;
        if (g_fc[o] < CL) s = g_ls[o];
    }
}

__global__ void scan_s5()
{
    const int h = blockIdx.x * blockDim.x + threadIdx.x;
    const int b = blockIdx.y, c = blockIdx.z;
    const size_t co = ((size_t)c * Bsz + b) * Hsz + h;
    const int fc = g_fc[co];
    if (fc == 0) return;
    const __half sv = __float2half_rn(g_sinit[co]);
    __half* c1s = g_c1 + ((size_t)b * Ssz + c * CL) * 2 * Hsz + Hsz + h;
    for (int t = 0; t < fc; ++t)
        c1s[(size_t)t * 2 * Hsz] = sv;
}

// ---------------------------------------------------------------------------
// Multi-phase fp16 split-GEMM on mma.sync.
// Pipeline (proven R6): wait -> barrier -> issue(it+2) -> compute(it).
// B pairs loaded via ldmatrix.x4. LDSM swizzle-XOR hoisted (row-only mask).
// ---------------------------------------------------------------------------
struct GemmSpec {
    const __half* A[3];
    const __half* B[3];
    int lda[3];
    int ldb[3];
    int cum[4];
};

template<int NPH, int T, bool DO_TANH>
__global__ __launch_bounds__(256, 2)
void gemm_mma(const __grid_constant__ GemmSpec spec,
              const float* __restrict__ bias, float* __restrict__ C)
{
    extern __shared__ __align__(1024) char smem[];
    const uint32_t sb = smem_u32(smem);
    const int tid = threadIdx.x, lane = tid & 31, wid = tid >> 5;
    const int wm = wid >> 2, wn = wid & 3;
    const int m0 = blockIdx.y * 128, n0 = blockIdx.x * 128;

    float acc[4][4][4];
#pragma unroll
    for (int i = 0; i < 4; ++i)
#pragma unroll
        for (int j = 0; j < 4; ++j)
#pragma unroll
            for (int k = 0; k < 4; ++k) acc[i][j][k] = 0.0f;

    // Hoisted LDSM addressing: offset = row*128 + (col ^ ((row&7)<<4)).
    uint32_t aBase[4], aXm;
    {
        int r0 = wm * 64 + (lane & 15);
#pragma unroll
        for (int mt = 0; mt < 4; ++mt) aBase[mt] = (uint32_t)((r0 + mt * 16) * 128);
        aXm = (uint32_t)(((r0 & 7) << 4));
    }
    const uint32_t aCol0 = (uint32_t)((lane >> 4) * 16);
    uint32_t bBase[2], bXm;
    {
        int mat = lane >> 3;
        int rb = wn * 32 + (mat >> 1) * 8 + (lane & 7);
#pragma unroll
        for (int np = 0; np < 2; ++np) bBase[np] = (uint32_t)((rb + np * 16) * 128);
        bXm = (uint32_t)(((rb & 7) << 4));
    }
    const uint32_t bCol0 = (uint32_t)(((lane >> 3) & 1) * 16);

    auto issue_loads = [&](int it) {
        int ph = 0;
#pragma unroll
        for (int p = 0; p < NPH - 1; ++p) if (it >= spec.cum[p + 1]) ph = p + 1;
        const int kt = (it - spec.cum[ph]) * 64;
        const int lda = spec.lda[ph], ldb = spec.ldb[ph];
        const char* Apc = (const char*)spec.A[ph];
        const char* Bpc = (const char*)spec.B[ph];
        const uint32_t sA = sb + (it % 3) * STAGE_BYTES;
        const uint32_t sB = sA + 16384;
#pragma unroll
        for (int i = 0; i < 4; ++i) {
            int id = tid + 256 * i;
            int r = id >> 3, cb = (id & 7) * 16;
            CP_ASYNC16(sA + SWZ128(r * 128 + cb),
                       Apc + ((size_t)(m0 + r) * lda + kt) * 2 + cb);
            CP_ASYNC16(sB + SWZ128(r * 128 + cb),
                       Bpc + ((size_t)(n0 + r) * ldb + kt) * 2 + cb);
        }
    };

    issue_loads(0); CP_COMMIT();
    issue_loads(1); CP_COMMIT();

#pragma unroll 1
    for (int it = 0; it < T; ++it) {
        if (it + 1 < T) { CP_WAIT1(); } else { CP_WAIT0(); }
        __syncthreads();
        if (it + 2 < T) { issue_loads(it + 2); CP_COMMIT(); }

        const uint32_t sA = sb + (it % 3) * STAGE_BYTES;
        const uint32_t sB = sA + 16384;
#pragma unroll
        for (int kk = 0; kk < 4; ++kk) {
            uint32_t aF[4][4], bF[4][2];
            const uint32_t aCol = ((uint32_t)(kk * 32) + aCol0) ^ aXm;
            const uint32_t bCol = ((uint32_t)(kk * 32) + bCol0) ^ bXm;
#pragma unroll
            for (int mt = 0; mt < 4; ++mt)
                ldsm_x4(aF[mt], sA + aBase[mt] + aCol);
#pragma unroll
            for (int np = 0; np < 2; ++np) {
                uint32_t r4[4];
                ldsm_x4(r4, sB + bBase[np] + bCol);
                bF[2 * np][0] = r4[0]; bF[2 * np][1] = r4[1];
                bF[2 * np + 1][0] = r4[2]; bF[2 * np + 1][1] = r4[3];
            }
#pragma unroll
            for (int mt = 0; mt < 4; ++mt)
#pragma unroll
                for (int nt = 0; nt < 4; ++nt)
                    mma_fp16(acc[mt][nt], aF[mt], bF[nt]);
        }
    }

    const int gid = lane >> 2, tig = lane & 3;
#pragma unroll
    for (int mt = 0; mt < 4; ++mt) {
#pragma unroll
        for (int nt = 0; nt < 4; ++nt) {
            int col = n0 + wn * 32 + nt * 8 + 2 * tig;
            float2 bv = *reinterpret_cast<const float2*>(&bias[col]);
            int r0 = m0 + wm * 64 + mt * 16 + gid;
            float2 v0, v1;
            v0.x = acc[mt][nt][0] + bv.x; v0.y = acc[mt][nt][1] + bv.y;
            v1.x = acc[mt][nt][2] + bv.x; v1.y = acc[mt][nt][3] + bv.y;
            if (DO_TANH) {
                v0.x = tanhf(v0.x); v0.y = tanhf(v0.y);
                v1.x = tanhf(v1.x); v1.y = tanhf(v1.y);
            }
            *reinterpret_cast<float2*>(&C[(size_t)r0 * NG + col]) = v0;
            *reinterpret_cast<float2*>(&C[(size_t)(r0 + 8) * NG + col]) = v1;
        }
    }
}

// ---------------------------------------------------------------------------
extern "C" void kernel_launch(void* const* d_in, const int* in_sizes, int n_in,
                              void* d_out, int out_size)
{
    const float* x        = (const float*)d_in[0];
    const float* W_in     = (const float*)d_in[1];
    const float* b_in     = (const float*)d_in[2];
    const float* leak_tau = (const float*)d_in[3];
    const float* thr      = (const float*)d_in[4];
    const float* W_out    = (const float*)d_in[5];
    const float* b_out    = (const float*)d_in[6];
    float* out = (float*)d_out;

    float* pI; cudaGetSymbolAddress((void**)&pI, g_I);
    __half *xa, *xb, *c1, *c2v, *Wi1, *Wi2, *Wo1;
    cudaGetSymbolAddress((void**)&xa,  g_xa);
    cudaGetSymbolAddress((void**)&xb,  g_xb);
    cudaGetSymbolAddress((void**)&c1,  g_c1);
    cudaGetSymbolAddress((void**)&c2v, g_c2v);
    cudaGetSymbolAddress((void**)&Wi1, g_Wi1);
    cudaGetSymbolAddress((void**)&Wi2, g_Wi2);
    cudaGetSymbolAddress((void**)&Wo1, g_Wo1);

    cudaFuncSetAttribute(gemm_mma<3, 48, false>,
                         cudaFuncAttributeMaxDynamicSharedMemorySize, GEMM_SMEM);
    cudaFuncSetAttribute(gemm_mma<2, 48, true>,
                         cudaFuncAttributeMaxDynamicSharedMemorySize, GEMM_SMEM);

    // Splits (fp16 2-way; W_out only needs the primary fp16 image)
    split2_x<<<2048, 256>>>(x, xa, xb, (size_t)Msz * INsz);
    transpose_split2<<<dim3(Hsz / 32, INsz / 32), dim3(32, 8)>>>(
        W_in, INsz, Hsz, Wi1, Wi2);
    transpose_split2<<<dim3(Hsz / 32, (2 * Hsz) / 32), dim3(32, 8)>>>(
        W_out, 2 * Hsz, Hsz, Wo1, nullptr);

    // GEMM1: I = x @ W_in + b_in — 3-term fp16 split, small terms first:
    //   (2,1) xb*Wi1, (1,2) xa*Wi2, (1,1) xa*Wi1  (16 iters each)
    //   (Pre-threshold: residual terms REQUIRED — flip amplification.)
    {
        GemmSpec g = {};
        const __half* As[3] = { xb,  xa,  xa  };
        const __half* Bs[3] = { Wi1, Wi2, Wi1 };
        for (int p = 0; p < 3; ++p) {
            g.A[p] = As[p]; g.B[p] = Bs[p];
            g.lda[p] = INsz; g.ldb[p] = INsz;
            g.cum[p] = p * 16;
        }
        g.cum[3] = 48;
        gemm_mma<3, 48, false><<<dim3(Hsz / 128, Msz / 128), 256, GEMM_SMEM>>>(
            g, b_in, pI);
    }

    // Chunked parallel scan -> c1, c2v
    {
        dim3 gc(Hsz / 256, Bsz, NC);
        dim3 gs(Hsz / 256, Bsz, 1);
        scan_s1<<<gc, 256>>>(leak_tau);
        scan_s2<<<gs, 256>>>(leak_tau);
        scan_s3<<<gc, 256>>>(leak_tau, thr);
        scan_s4<<<gs, 256>>>();
        scan_s5<<<gc, 256>>>();
    }

    // GEMM2: out = tanh(comb @ W_out + b_out).
    // Post-threshold errors are smooth + tanh-attenuated: W_out residual
    // term dropped (ε≈3.6e-4 pre-tanh → ~2.9e-4 rel). Kept terms:
    //   (2,1) c2v@Wo1 (16 iters, small first), (1,1) c1@Wo1 (32 iters)
    {
        GemmSpec g = {};
        g.A[0] = c2v; g.B[0] = Wo1; g.lda[0] = 1024; g.ldb[0] = 2048;
        g.A[1] = c1;  g.B[1] = Wo1; g.lda[1] = 2048; g.ldb[1] = 2048;
        g.A[2] = c1;  g.B[2] = Wo1; g.lda[2] = 2048; g.ldb[2] = 2048; // unused
        g.cum[0] = 0; g.cum[1] = 16; g.cum[2] = 48; g.cum[3] = 48;
        gemm_mma<2, 48, true><<<dim3(NG / 128, Msz / 128), 256, GEMM_SMEM>>>(
            g, b_out, out);
    }
}

// round 12
// speedup vs baseline: 5.2711x; 1.1578x over previous
#include <cuda_runtime.h>
#include <cuda_fp16.h>
#include <stdint.h>
#include <math.h>

// ---------------------------------------------------------------------------
// Problem dims
// ---------------------------------------------------------------------------
namespace {
constexpr int Bsz  = 16;
constexpr int Ssz  = 2048;
constexpr int Hsz  = 1024;
constexpr int INsz = 1024;
constexpr int Msz  = Bsz * Ssz;       // 32768
constexpr int NG   = 1024;
constexpr int STAGE_BYTES = 32768;    // 16KB A + 16KB B per stage
constexpr int GEMM_SMEM = 3 * STAGE_BYTES;  // 96 KiB, 3-stage ring
constexpr int NC   = 32;              // scan chunks
constexpr int CL   = Ssz / NC;        // 64 timesteps per chunk
}

// ---------------------------------------------------------------------------
// Scratch (__device__ globals; no allocation allowed)
// ---------------------------------------------------------------------------
__device__ float g_I[(size_t)Msz * Hsz];                   // 128 MiB
__device__ __half g_xa[(size_t)Msz * INsz];                // x 2-way fp16 split
__device__ __half g_xb[(size_t)Msz * INsz];
__device__ __half g_c1[(size_t)Msz * 2 * Hsz];             // [M][2048]: v | s
__device__ __half g_Wi1[(size_t)Hsz * INsz];               // W_in^T fp16 splits [N][K]
__device__ __half g_Wi2[(size_t)Hsz * INsz];
__device__ __half g_Wo1[(size_t)Hsz * 2 * Hsz];            // W_out^T fp16 [N][2048]
// scan pipeline scratch: [c][b][h]
__device__ float g_vend [(size_t)NC * Bsz * Hsz];
__device__ float g_vinit[(size_t)NC * Bsz * Hsz];
__device__ int   g_fc   [(size_t)NC * Bsz * Hsz];
__device__ float g_ls   [(size_t)NC * Bsz * Hsz];
__device__ float g_sinit[(size_t)NC * Bsz * Hsz];

// ---------------------------------------------------------------------------
// PTX helpers (base sm_80+ features only)
// ---------------------------------------------------------------------------
#define SWZ128(o) ((o) ^ (((o) >> 3) & 0x70))

__device__ __forceinline__ uint32_t smem_u32(const void* p) {
    uint32_t a;
    asm("{ .reg .u64 t; cvta.to.shared.u64 t, %1; cvt.u32.u64 %0, t; }"
        : "=r"(a) : "l"(p));
    return a;
}
#define CP_ASYNC16(s, g) \
    asm volatile("cp.async.cg.shared.global [%0], [%1], 16;" :: "r"(s), "l"(g))
#define CP_COMMIT()  asm volatile("cp.async.commit_group;" ::: "memory")
#define CP_WAIT0()   asm volatile("cp.async.wait_group 0;" ::: "memory")
#define CP_WAIT1()   asm volatile("cp.async.wait_group 1;" ::: "memory")

__device__ __forceinline__ void ldsm_x4(uint32_t r[4], uint32_t addr) {
    asm volatile("ldmatrix.sync.aligned.m8n8.x4.shared.b16 {%0,%1,%2,%3}, [%4];"
        : "=r"(r[0]), "=r"(r[1]), "=r"(r[2]), "=r"(r[3]) : "r"(addr));
}
__device__ __forceinline__ void mma_fp16(float c[4], const uint32_t a[4],
                                         const uint32_t b[2]) {
    asm volatile(
        "mma.sync.aligned.m16n8k16.row.col.f32.f16.f16.f32 "
        "{%0,%1,%2,%3}, {%4,%5,%6,%7}, {%8,%9}, {%0,%1,%2,%3};"
        : "+f"(c[0]), "+f"(c[1]), "+f"(c[2]), "+f"(c[3])
        : "r"(a[0]), "r"(a[1]), "r"(a[2]), "r"(a[3]), "r"(b[0]), "r"(b[1]));
}

// ---------------------------------------------------------------------------
// Split kernels (fp16 2-way)
// ---------------------------------------------------------------------------
__global__ void split2_x(const float* __restrict__ x, __half* __restrict__ o1,
                         __half* __restrict__ o2, size_t n)
{
    size_t i = (size_t)blockIdx.x * blockDim.x + threadIdx.x;
    size_t stride = (size_t)gridDim.x * blockDim.x;
    for (; i < n; i += stride) {
        float w = x[i];
        __half a = __float2half_rn(w);
        float r = w - __half2float(a);
        o1[i] = a; o2[i] = __float2half_rn(r);
    }
}

// W[K][N] fp32 -> o[N][K] fp16 2-way split (o2 optional)
__global__ void transpose_split2(const float* __restrict__ W, int K, int N,
                                 __half* __restrict__ o1,
                                 __half* __restrict__ o2)
{
    __shared__ float t[32][33];
    int n0 = blockIdx.x * 32, k0 = blockIdx.y * 32;
    int tx = threadIdx.x, ty = threadIdx.y;   // (32, 8)
#pragma unroll
    for (int i = 0; i < 4; ++i)
        t[ty + i * 8][tx] = W[(size_t)(k0 + ty + i * 8) * N + n0 + tx];
    __syncthreads();
#pragma unroll
    for (int i = 0; i < 4; ++i) {
        int nn = n0 + ty + i * 8, k = k0 + tx;
        float w = t[tx][ty + i * 8];
        __half a = __float2half_rn(w);
        o1[(size_t)nn * K + k] = a;
        if (o2) {
            float r = w - __half2float(a);
            o2[(size_t)nn * K + k] = __float2half_rn(r);
        }
    }
}

// ---------------------------------------------------------------------------
// Chunked parallel hysteresis scan (proven in R8).
// ---------------------------------------------------------------------------
__device__ __forceinline__ float sig_alpha(const float* lt, int h) {
    return 1.0f / (1.0f + expf(lt[h]));
}

__global__ void scan_s1(const float* __restrict__ leak_tau)
{
    const int h = blockIdx.x * blockDim.x + threadIdx.x;
    const int b = blockIdx.y, c = blockIdx.z;
    const float alpha = sig_alpha(leak_tau, h);
    const float* Ip = g_I + ((size_t)b * Ssz + c * CL) * Hsz + h;
    float v = 0.0f;
#pragma unroll 4
    for (int t = 0; t < CL; ++t)
        v = fmaf(alpha, v, Ip[(size_t)t * Hsz]);
    g_vend[((size_t)c * Bsz + b) * Hsz + h] = v;
}

__global__ void scan_s2(const float* __restrict__ leak_tau)
{
    const int h = blockIdx.x * blockDim.x + threadIdx.x;
    const int b = blockIdx.y;
    const float alpha = sig_alpha(leak_tau, h);
    const float aL = powf(alpha, (float)CL);
    float v = 0.0f;
    for (int c = 0; c < NC; ++c) {
        size_t o = ((size_t)c * Bsz + b) * Hsz + h;
        g_vinit[o] = v;
        v = fmaf(aL, v, g_vend[o]);
    }
}

__global__ void scan_s3(const float* __restrict__ leak_tau,
                        const float* __restrict__ thr_arr)
{
    const int h = blockIdx.x * blockDim.x + threadIdx.x;
    const int b = blockIdx.y, c = blockIdx.z;
    const float alpha = sig_alpha(leak_tau, h);
    const float th = thr_arr[h];
    const size_t co = ((size_t)c * Bsz + b) * Hsz + h;
    float v = g_vinit[co];

    const int t0 = c * CL;
    const float* Ip = g_I + ((size_t)b * Ssz + t0) * Hsz + h;
    __half* c1 = g_c1 + ((size_t)b * Ssz + t0) * 2 * Hsz + h;

    int fc = CL;
    float s = 0.0f;
#pragma unroll 4
    for (int t = 0; t < CL; ++t) {
        v = fmaf(alpha, v, Ip[(size_t)t * Hsz]);
        bool up = v > th, dn = v < -th;
        if (up | dn) {
            if (fc == CL) fc = t;
            s = up ? 1.0f : -1.0f;
        }
        c1[(size_t)t * 2 * Hsz] = __float2half_rn(v);
        if (fc != CL)
            c1[(size_t)t * 2 * Hsz + Hsz] = __float2half_rn(s);
    }
    g_fc[co] = fc;
    g_ls[co] = s;
}

__global__ void scan_s4()
{
    const int h = blockIdx.x * blockDim.x + threadIdx.x;
    const int b = blockIdx.y;
    float s = -1.0f;
    for (int c = 0; c < NC; ++c) {
        size_t o = ((size_t)c * Bsz + b) * Hsz + h;
        g_sinit[o] = s;
        if (g_fc[o] < CL) s = g_ls[o];
    }
}

__global__ void scan_s5()
{
    const int h = blockIdx.x * blockDim.x + threadIdx.x;
    const int b = blockIdx.y, c = blockIdx.z;
    const size_t co = ((size_t)c * Bsz + b) * Hsz + h;
    const int fc = g_fc[co];
    if (fc == 0) return;
    const __half sv = __float2half_rn(g_sinit[co]);
    __half* c1s = g_c1 + ((size_t)b * Ssz + c * CL) * 2 * Hsz + Hsz + h;
    for (int t = 0; t < fc; ++t)
        c1s[(size_t)t * 2 * Hsz] = sv;
}

// ---------------------------------------------------------------------------
// Multi-phase fp16 split-GEMM on mma.sync.
// Pipeline (proven R6): wait -> barrier -> issue(it+2) -> compute(it).
// B pairs loaded via ldmatrix.x4. LDSM swizzle-XOR hoisted (row-only mask).
// ---------------------------------------------------------------------------
struct GemmSpec {
    const __half* A[3];
    const __half* B[3];
    int lda[3];
    int ldb[3];
    int cum[4];
};

template<int NPH, int T, bool DO_TANH>
__global__ __launch_bounds__(256, 2)
void gemm_mma(const __grid_constant__ GemmSpec spec,
              const float* __restrict__ bias, float* __restrict__ C)
{
    extern __shared__ __align__(1024) char smem[];
    const uint32_t sb = smem_u32(smem);
    const int tid = threadIdx.x, lane = tid & 31, wid = tid >> 5;
    const int wm = wid >> 2, wn = wid & 3;
    const int m0 = blockIdx.y * 128, n0 = blockIdx.x * 128;

    float acc[4][4][4];
#pragma unroll
    for (int i = 0; i < 4; ++i)
#pragma unroll
        for (int j = 0; j < 4; ++j)
#pragma unroll
            for (int k = 0; k < 4; ++k) acc[i][j][k] = 0.0f;

    // Hoisted LDSM addressing: offset = row*128 + (col ^ ((row&7)<<4)).
    uint32_t aBase[4], aXm;
    {
        int r0 = wm * 64 + (lane & 15);
#pragma unroll
        for (int mt = 0; mt < 4; ++mt) aBase[mt] = (uint32_t)((r0 + mt * 16) * 128);
        aXm = (uint32_t)(((r0 & 7) << 4));
    }
    const uint32_t aCol0 = (uint32_t)((lane >> 4) * 16);
    uint32_t bBase[2], bXm;
    {
        int mat = lane >> 3;
        int rb = wn * 32 + (mat >> 1) * 8 + (lane & 7);
#pragma unroll
        for (int np = 0; np < 2; ++np) bBase[np] = (uint32_t)((rb + np * 16) * 128);
        bXm = (uint32_t)(((rb & 7) << 4));
    }
    const uint32_t bCol0 = (uint32_t)(((lane >> 3) & 1) * 16);

    auto issue_loads = [&](int it) {
        int ph = 0;
#pragma unroll
        for (int p = 0; p < NPH - 1; ++p) if (it >= spec.cum[p + 1]) ph = p + 1;
        const int kt = (it - spec.cum[ph]) * 64;
        const int lda = spec.lda[ph], ldb = spec.ldb[ph];
        const char* Apc = (const char*)spec.A[ph];
        const char* Bpc = (const char*)spec.B[ph];
        const uint32_t sA = sb + (it % 3) * STAGE_BYTES;
        const uint32_t sB = sA + 16384;
#pragma unroll
        for (int i = 0; i < 4; ++i) {
            int id = tid + 256 * i;
            int r = id >> 3, cb = (id & 7) * 16;
            CP_ASYNC16(sA + SWZ128(r * 128 + cb),
                       Apc + ((size_t)(m0 + r) * lda + kt) * 2 + cb);
            CP_ASYNC16(sB + SWZ128(r * 128 + cb),
                       Bpc + ((size_t)(n0 + r) * ldb + kt) * 2 + cb);
        }
    };

    issue_loads(0); CP_COMMIT();
    issue_loads(1); CP_COMMIT();

#pragma unroll 1
    for (int it = 0; it < T; ++it) {
        if (it + 1 < T) { CP_WAIT1(); } else { CP_WAIT0(); }
        __syncthreads();
        if (it + 2 < T) { issue_loads(it + 2); CP_COMMIT(); }

        const uint32_t sA = sb + (it % 3) * STAGE_BYTES;
        const uint32_t sB = sA + 16384;
#pragma unroll
        for (int kk = 0; kk < 4; ++kk) {
            uint32_t aF[4][4], bF[4][2];
            const uint32_t aCol = ((uint32_t)(kk * 32) + aCol0) ^ aXm;
            const uint32_t bCol = ((uint32_t)(kk * 32) + bCol0) ^ bXm;
#pragma unroll
            for (int mt = 0; mt < 4; ++mt)
                ldsm_x4(aF[mt], sA + aBase[mt] + aCol);
#pragma unroll
            for (int np = 0; np < 2; ++np) {
                uint32_t r4[4];
                ldsm_x4(r4, sB + bBase[np] + bCol);
                bF[2 * np][0] = r4[0]; bF[2 * np][1] = r4[1];
                bF[2 * np + 1][0] = r4[2]; bF[2 * np + 1][1] = r4[3];
            }
#pragma unroll
            for (int mt = 0; mt < 4; ++mt)
#pragma unroll
                for (int nt = 0; nt < 4; ++nt)
                    mma_fp16(acc[mt][nt], aF[mt], bF[nt]);
        }
    }

    const int gid = lane >> 2, tig = lane & 3;
#pragma unroll
    for (int mt = 0; mt < 4; ++mt) {
#pragma unroll
        for (int nt = 0; nt < 4; ++nt) {
            int col = n0 + wn * 32 + nt * 8 + 2 * tig;
            float2 bv = *reinterpret_cast<const float2*>(&bias[col]);
            int r0 = m0 + wm * 64 + mt * 16 + gid;
            float2 v0, v1;
            v0.x = acc[mt][nt][0] + bv.x; v0.y = acc[mt][nt][1] + bv.y;
            v1.x = acc[mt][nt][2] + bv.x; v1.y = acc[mt][nt][3] + bv.y;
            if (DO_TANH) {
                v0.x = tanhf(v0.x); v0.y = tanhf(v0.y);
                v1.x = tanhf(v1.x); v1.y = tanhf(v1.y);
            }
            *reinterpret_cast<float2*>(&C[(size_t)r0 * NG + col]) = v0;
            *reinterpret_cast<float2*>(&C[(size_t)(r0 + 8) * NG + col]) = v1;
        }
    }
}

// ---------------------------------------------------------------------------
extern "C" void kernel_launch(void* const* d_in, const int* in_sizes, int n_in,
                              void* d_out, int out_size)
{
    const float* x        = (const float*)d_in[0];
    const float* W_in     = (const float*)d_in[1];
    const float* b_in     = (const float*)d_in[2];
    const float* leak_tau = (const float*)d_in[3];
    const float* thr      = (const float*)d_in[4];
    const float* W_out    = (const float*)d_in[5];
    const float* b_out    = (const float*)d_in[6];
    float* out = (float*)d_out;

    float* pI; cudaGetSymbolAddress((void**)&pI, g_I);
    __half *xa, *xb, *c1, *Wi1, *Wi2, *Wo1;
    cudaGetSymbolAddress((void**)&xa,  g_xa);
    cudaGetSymbolAddress((void**)&xb,  g_xb);
    cudaGetSymbolAddress((void**)&c1,  g_c1);
    cudaGetSymbolAddress((void**)&Wi1, g_Wi1);
    cudaGetSymbolAddress((void**)&Wi2, g_Wi2);
    cudaGetSymbolAddress((void**)&Wo1, g_Wo1);

    cudaFuncSetAttribute(gemm_mma<3, 48, false>,
                         cudaFuncAttributeMaxDynamicSharedMemorySize, GEMM_SMEM);
    cudaFuncSetAttribute(gemm_mma<1, 32, true>,
                         cudaFuncAttributeMaxDynamicSharedMemorySize, GEMM_SMEM);

    // Splits (fp16 2-way; W_out only needs the primary fp16 image)
    split2_x<<<2048, 256>>>(x, xa, xb, (size_t)Msz * INsz);
    transpose_split2<<<dim3(Hsz / 32, INsz / 32), dim3(32, 8)>>>(
        W_in, INsz, Hsz, Wi1, Wi2);
    transpose_split2<<<dim3(Hsz / 32, (2 * Hsz) / 32), dim3(32, 8)>>>(
        W_out, 2 * Hsz, Hsz, Wo1, nullptr);

    // GEMM1: I = x @ W_in + b_in — 3-term fp16 split, small terms first:
    //   (2,1) xb*Wi1, (1,2) xa*Wi2, (1,1) xa*Wi1  (16 iters each)
    //   (Pre-threshold: residual terms REQUIRED — flip amplification.)
    {
        GemmSpec g = {};
        const __half* As[3] = { xb,  xa,  xa  };
        const __half* Bs[3] = { Wi1, Wi2, Wi1 };
        for (int p = 0; p < 3; ++p) {
            g.A[p] = As[p]; g.B[p] = Bs[p];
            g.lda[p] = INsz; g.ldb[p] = INsz;
            g.cum[p] = p * 16;
        }
        g.cum[3] = 48;
        gemm_mma<3, 48, false><<<dim3(Hsz / 128, Msz / 128), 256, GEMM_SMEM>>>(
            g, b_in, pI);
    }

    // Chunked parallel scan -> c1
    {
        dim3 gc(Hsz / 256, Bsz, NC);
        dim3 gs(Hsz / 256, Bsz, 1);
        scan_s1<<<gc, 256>>>(leak_tau);
        scan_s2<<<gs, 256>>>(leak_tau);
        scan_s3<<<gc, 256>>>(leak_tau, thr);
        scan_s4<<<gs, 256>>>();
        scan_s5<<<gc, 256>>>();
    }

    // GEMM2: out = tanh(comb @ W_out + b_out).
    // Post-threshold errors are smooth + tanh-attenuated: BOTH residual
    // terms dropped (calibrated: Wo2 term added 2.3e-4; c2v term adds
    // ~1.6e-4 in quadrature). Single plain fp16 GEMM: c1 @ Wo1, 32 iters.
    {
        GemmSpec g = {};
        g.A[0] = c1; g.B[0] = Wo1; g.lda[0] = 2048; g.ldb[0] = 2048;
        g.A[1] = c1; g.B[1] = Wo1; g.lda[1] = 2048; g.ldb[1] = 2048; // unused
        g.A[2] = c1; g.B[2] = Wo1; g.lda[2] = 2048; g.ldb[2] = 2048; // unused
        g.cum[0] = 0; g.cum[1] = 32; g.cum[2] = 32; g.cum[3] = 32;
        gemm_mma<1, 32, true><<<dim3(NG / 128, Msz / 128), 256, GEMM_SMEM>>>(
            g, b_out, out);
    }
}